// round 8
// baseline (speedup 1.0000x reference)
#include <cuda_runtime.h>
#include <math.h>
#include <stdint.h>

// ---------------- constants ----------------
#define BB 64
#define TT 20
#define EE 300
#define CEE 1024
#define ANSN 3000
#define HH 512
#define NN 256
#define WW 64
#define RR 4
#define RWRW 256
#define IFTOT 471
#define CLIPV 20.0f
#define EPSV 1e-6f

// state offsets inside g_state
#define OFF_MEM    0            // B*N*W
#define OFF_LINK   1048576      // B*N*N
#define OFF_PREC   5242880      // B*N
#define OFF_WR     5259264      // B*R*N
#define OFF_WW     5324800      // B*N
#define OFF_USAGE  5341184      // B*N
#define OFF_RVEC   5357568      // B*R*W
#define OFF_H      5373952      // B*H
#define OFF_C      5406720      // B*H (unused; c is double-buffered in g_cbuf)
#define STATE_TOT  5439488

// g_part layout (floats)
#define GSTRIDE    131072       // 64*2048  gates partial stride (7 max -> [0, 917504))
#define XIP        917504       // xi partials base
#define XISTRIDE   30144        // 64*471
#define OUTP       1048576      // out_hc partials base
#define OUTSTRIDE  65536        // 64*1024

// ---------------- device globals ----------------
__device__ __align__(16) float g_state[STATE_TOT];
__device__ __align__(16) float g_cbuf[2 * BB * HH];
__device__ __align__(16) float g_qv[BB * TT * EE];
__device__ __align__(16) float g_pre[BB * TT * 2048];
__device__ __align__(16) float g_part[8 * 64 * 3072];
__device__ __align__(16) float g_outbuf[BB * CEE];
__device__ __align__(16) float g_qsum[BB * CEE];
__device__ __align__(16) float g_imgf[BB * CEE];
__device__ __align__(16) float g_comb[BB * CEE];
__device__ __align__(16) float g_last[BB * (CEE + RWRW)];
__device__ __align__(16) float g_fc1[BB * ANSN];

// ---------------- helpers ----------------
__device__ __forceinline__ float sigf(float x) { return 1.0f / (1.0f + expf(-x)); }
__device__ __forceinline__ float softplusf(float x) {
    return fmaxf(x, 0.0f) + log1pf(expf(-fabsf(x)));
}
__device__ __forceinline__ float blk_max(float v, volatile float* red, int tid) {
    red[tid] = v; __syncthreads();
    for (int s = 128; s > 0; s >>= 1) {
        if (tid < s) red[tid] = fmaxf((float)red[tid], (float)red[tid + s]);
        __syncthreads();
    }
    float r = red[0]; __syncthreads();
    return r;
}
__device__ __forceinline__ float blk_sum(float v, volatile float* red, int tid) {
    red[tid] = v; __syncthreads();
    for (int s = 128; s > 0; s >>= 1) {
        if (tid < s) red[tid] = (float)red[tid] + (float)red[tid + s];
        __syncthreads();
    }
    float r = red[0]; __syncthreads();
    return r;
}

// ---------------- misc kernels ----------------
__global__ void k_zero(float* p, int n) {
    int i = blockIdx.x * blockDim.x + threadIdx.x;
    if (i < n) p[i] = 0.0f;
}

__global__ void k_embed(const int* __restrict__ qst, const float* __restrict__ emb) {
    int i = blockIdx.x * blockDim.x + threadIdx.x;
    if (i >= BB * TT * EE) return;
    int e = i % EE;
    int bt = i / EE;
    int tok = qst[bt];
    g_qv[i] = tanhf(emb[(size_t)tok * EE + e]);
}

// ---------------- GEMM: 64x64 tile, 256 threads, 4x4 register blocking ----------------
struct SegP {
    const float* A[8];
    const float* W[8];
    int K[8];
    int lda[8];
    int Nout[8];
    long coff[8];          // partial output offset into Cout (split mode)
};

// gridDim.z>1: one segment per z, partials to Cout + coff[z]
// gridDim.z==1: loop all nseg segments, direct store to Cout (Nout[0])
__global__ void gemm64(SegP p, int nseg, float* __restrict__ Cout) {
    __shared__ __align__(16) float As[16][68];
    __shared__ __align__(16) float Ws[16][68];
    int tid = threadIdx.x;
    int tx = tid & 15;
    int ty = tid >> 4;
    int col0 = blockIdx.x * 64;
    int row0 = blockIdx.y * 64;
    float acc[4][4] = {};

    int z0, z1;
    if (gridDim.z > 1) { z0 = blockIdx.z; z1 = z0 + 1; } else { z0 = 0; z1 = nseg; }
    int Nout = p.Nout[z0];
    if (col0 >= Nout) return;
    bool nvec = ((Nout & 3) == 0);

    int lm = tid >> 2;            // A loader row 0..63
    int lkb = (tid & 3) * 4;      // A loader k offset
    int lkk = tid >> 4;           // W loader k 0..15
    int lnb = (tid & 15) * 4;     // W loader col offset

    for (int z = z0; z < z1; z++) {
        const float* A = p.A[z];
        const float* W = p.W[z];
        int K = p.K[z];
        int lda = p.lda[z];
        for (int k0 = 0; k0 < K; k0 += 16) {
            {
                const float* Ap = A + (size_t)(row0 + lm) * lda + k0 + lkb;
#pragma unroll
                for (int u = 0; u < 4; u++)
                    As[lkb + u][lm] = (k0 + lkb + u < K) ? Ap[u] : 0.0f;
            }
            {
                int kg = k0 + lkk;
                int c = col0 + lnb;
                if (nvec && kg < K && c + 3 < Nout) {
                    float4 v = *(const float4*)&W[(size_t)kg * Nout + c];
                    Ws[lkk][lnb] = v.x; Ws[lkk][lnb + 1] = v.y;
                    Ws[lkk][lnb + 2] = v.z; Ws[lkk][lnb + 3] = v.w;
                } else {
#pragma unroll
                    for (int u = 0; u < 4; u++)
                        Ws[lkk][lnb + u] = (kg < K && c + u < Nout)
                                           ? W[(size_t)kg * Nout + c + u] : 0.0f;
                }
            }
            __syncthreads();
#pragma unroll
            for (int kk = 0; kk < 16; kk++) {
                float4 a = *(const float4*)&As[kk][ty * 4];
                float4 w = *(const float4*)&Ws[kk][tx * 4];
                acc[0][0] += a.x * w.x; acc[0][1] += a.x * w.y;
                acc[0][2] += a.x * w.z; acc[0][3] += a.x * w.w;
                acc[1][0] += a.y * w.x; acc[1][1] += a.y * w.y;
                acc[1][2] += a.y * w.z; acc[1][3] += a.y * w.w;
                acc[2][0] += a.z * w.x; acc[2][1] += a.z * w.y;
                acc[2][2] += a.z * w.z; acc[2][3] += a.z * w.w;
                acc[3][0] += a.w * w.x; acc[3][1] += a.w * w.y;
                acc[3][2] += a.w * w.z; acc[3][3] += a.w * w.w;
            }
            __syncthreads();
        }
    }

    float* Cbase = Cout + ((gridDim.z > 1) ? p.coff[blockIdx.z] : 0);
#pragma unroll
    for (int i = 0; i < 4; i++) {
        int row = row0 + ty * 4 + i;
#pragma unroll
        for (int j = 0; j < 4; j++) {
            int c = col0 + tx * 4 + j;
            if (c < Nout)
                Cbase[(size_t)row * Nout + c] = acc[i][j];
        }
    }
}

// ---------------- fused LSTM + xi/out_hc GEMM ----------------
// grid (16, 1, 8): z 0..3 -> xi GEMM (slice s=z), z 4..7 -> out_hc GEMM (slice s=z-4).
// Each block recomputes the LSTM for its 64x128 hc slice into k-major smem.
__global__ void k_xiout(const float* __restrict__ Wif, const float* __restrict__ Wout,
                        const float* __restrict__ bgate, int ngates, int use_pre, int t,
                        const float* __restrict__ c_in, float* __restrict__ c_out) {
    __shared__ __align__(16) float hcs[128][68];   // [k][row]
    __shared__ __align__(16) float Ws[16][68];
    int tid = threadIdx.x;
    int z = blockIdx.z, s = z & 3, bx = blockIdx.x;
    int Nout = (z < 4) ? IFTOT : CEE;
    int col0 = bx * 64;
    if (col0 >= Nout) return;

    // LSTM for hc slice s (cols j = s*128 + jj)
    bool writer = (z < 4 && bx == 0);
#pragma unroll 4
    for (int i = 0; i < 32; i++) {
        int e = tid + i * 256;          // 0..8191
        int row = e >> 7, jj = e & 127;
        int j = s * 128 + jj;
        float g[4];
#pragma unroll
        for (int q = 0; q < 4; q++) {
            int col = q * 512 + j;
            float v = bgate[col];
            if (use_pre) v += g_pre[((size_t)(row * TT + t)) * 2048 + col];
            for (int z2 = 0; z2 < ngates; z2++)
                v += g_part[(size_t)z2 * GSTRIDE + row * 2048 + col];
            g[q] = v;
        }
        float cc = sigf(g[1]) * c_in[row * 512 + j] + sigf(g[0]) * tanhf(g[2]);
        float hh = sigf(g[3]) * tanhf(cc);
        hcs[jj][row] = fminf(fmaxf(hh, -CLIPV), CLIPV);
        if (writer) {
            c_out[row * 512 + j] = cc;
            g_state[OFF_H + row * 512 + j] = hh;
        }
    }
    __syncthreads();

    const float* W;
    float* Cb;
    if (z < 4) { W = Wif + (size_t)(s * 128) * IFTOT;  Cb = g_part + XIP + (size_t)s * XISTRIDE; }
    else       { W = Wout + (size_t)(s * 128) * CEE;   Cb = g_part + OUTP + (size_t)s * OUTSTRIDE; }

    int tx = tid & 15, ty = tid >> 4;
    int lkk = tid >> 4, lnb = (tid & 15) * 4;
    bool nvec = ((Nout & 3) == 0);
    float acc[4][4] = {};
    for (int k0 = 0; k0 < 128; k0 += 16) {
        {
            int kg = k0 + lkk;
            int c = col0 + lnb;
            if (nvec && c + 3 < Nout) {
                float4 v = *(const float4*)&W[(size_t)kg * Nout + c];
                Ws[lkk][lnb] = v.x; Ws[lkk][lnb + 1] = v.y;
                Ws[lkk][lnb + 2] = v.z; Ws[lkk][lnb + 3] = v.w;
            } else {
#pragma unroll
                for (int u = 0; u < 4; u++)
                    Ws[lkk][lnb + u] = (c + u < Nout) ? W[(size_t)kg * Nout + c + u] : 0.0f;
            }
        }
        __syncthreads();
#pragma unroll
        for (int kk = 0; kk < 16; kk++) {
            float4 a = *(const float4*)&hcs[k0 + kk][ty * 4];
            float4 w = *(const float4*)&Ws[kk][tx * 4];
            acc[0][0] += a.x * w.x; acc[0][1] += a.x * w.y;
            acc[0][2] += a.x * w.z; acc[0][3] += a.x * w.w;
            acc[1][0] += a.y * w.x; acc[1][1] += a.y * w.y;
            acc[1][2] += a.y * w.z; acc[1][3] += a.y * w.w;
            acc[2][0] += a.z * w.x; acc[2][1] += a.z * w.y;
            acc[2][2] += a.z * w.z; acc[2][3] += a.z * w.w;
            acc[3][0] += a.w * w.x; acc[3][1] += a.w * w.y;
            acc[3][2] += a.w * w.z; acc[3][3] += a.w * w.w;
        }
        __syncthreads();
    }
#pragma unroll
    for (int i = 0; i < 4; i++) {
        int row = ty * 4 + i;
#pragma unroll
        for (int j = 0; j < 4; j++) {
            int c = col0 + tx * 4 + j;
            if (c < Nout)
                Cb[(size_t)row * Nout + c] = acc[i][j];
        }
    }
}

// ---------------- out-GEMM finish: rvec part + partials + bias + clip (+qsum) ----------------
__global__ void k_outfin(const float* __restrict__ A, const float* __restrict__ W,
                         const float* __restrict__ bias, float* __restrict__ outb,
                         float* __restrict__ qsum) {
    __shared__ __align__(16) float As[16][68];
    __shared__ __align__(16) float Ws[16][68];
    int tid = threadIdx.x;
    int tx = tid & 15, ty = tid >> 4;
    int col0 = blockIdx.x * 64;
    int lm = tid >> 2, lkb = (tid & 3) * 4;
    int lkk = tid >> 4, lnb = (tid & 15) * 4;
    float acc[4][4] = {};
    for (int k0 = 0; k0 < 256; k0 += 16) {
        {
            const float* Ap = A + (size_t)lm * 256 + k0 + lkb;
#pragma unroll
            for (int u = 0; u < 4; u++) As[lkb + u][lm] = Ap[u];
        }
        {
            float4 v = *(const float4*)&W[(size_t)(k0 + lkk) * CEE + col0 + lnb];
            Ws[lkk][lnb] = v.x; Ws[lkk][lnb + 1] = v.y;
            Ws[lkk][lnb + 2] = v.z; Ws[lkk][lnb + 3] = v.w;
        }
        __syncthreads();
#pragma unroll
        for (int kk = 0; kk < 16; kk++) {
            float4 a = *(const float4*)&As[kk][ty * 4];
            float4 w = *(const float4*)&Ws[kk][tx * 4];
            acc[0][0] += a.x * w.x; acc[0][1] += a.x * w.y;
            acc[0][2] += a.x * w.z; acc[0][3] += a.x * w.w;
            acc[1][0] += a.y * w.x; acc[1][1] += a.y * w.y;
            acc[1][2] += a.y * w.z; acc[1][3] += a.y * w.w;
            acc[2][0] += a.z * w.x; acc[2][1] += a.z * w.y;
            acc[2][2] += a.z * w.z; acc[2][3] += a.z * w.w;
            acc[3][0] += a.w * w.x; acc[3][1] += a.w * w.y;
            acc[3][2] += a.w * w.z; acc[3][3] += a.w * w.w;
        }
        __syncthreads();
    }
#pragma unroll
    for (int i = 0; i < 4; i++) {
        int row = ty * 4 + i;
#pragma unroll
        for (int j = 0; j < 4; j++) {
            int c = col0 + tx * 4 + j;
            float v = acc[i][j] + bias[c];
#pragma unroll
            for (int s2 = 0; s2 < 4; s2++)
                v += g_part[OUTP + (size_t)s2 * OUTSTRIDE + row * 1024 + c];
            v = fminf(fmaxf(v, -CLIPV), CLIPV);
            outb[row * 1024 + c] = v;
            if (qsum) qsum[row * 1024 + c] += v;
        }
    }
}

// ---------------- reduction / pointwise kernels ----------------
// act: 0 none, 2 tanh
__global__ void k_red(int nseg, int Nout, const float* __restrict__ bias,
                      float* __restrict__ out, int act) {
    int idx = blockIdx.x * blockDim.x + threadIdx.x;
    if (idx >= 64 * Nout) return;
    int j = idx % Nout;
    float v = bias[j];
    for (int z = 0; z < nseg; z++) v += g_part[(size_t)z * 64 * Nout + idx];
    if (act == 2) v = tanhf(v);
    out[idx] = v;
}

__global__ void k_comb(const float* __restrict__ img_b, int nseg) {
    __shared__ float red[256];
    int b = blockIdx.x;
    int tid = threadIdx.x;
    float s = 0;
    for (int j = tid; j < CEE; j += 256) {
        float v = img_b[j];
        for (int z = 0; z < nseg; z++) v += g_part[(size_t)z * 64 * 1024 + b * 1024 + j];
        g_imgf[b * CEE + j] = v;
        s += v * v;
    }
    float tot = blk_sum(s, red, tid);
    float inv = rsqrtf(tot);
    for (int j = tid; j < CEE; j += 256) {
        float v = g_imgf[b * CEE + j] * inv;
        g_comb[b * CEE + j] = tanhf(v * g_qsum[b * CEE + j] * (1.0f / (float)TT));
    }
}

__global__ void k_last() {
    int idx = blockIdx.x * blockDim.x + threadIdx.x;
    if (idx >= BB * (CEE + RWRW)) return;
    int b = idx / (CEE + RWRW);
    int j = idx % (CEE + RWRW);
    float v = (j < CEE) ? g_outbuf[b * CEE + j] : g_state[OFF_RVEC + b * 256 + (j - CEE)];
    g_last[idx] = tanhf(v);
}

// ---------------- fused per-batch DNC memory kernel ----------------
__global__ void k_dnc(const float* __restrict__ bif) {
    __shared__ float wro[4][256];
    __shared__ float sh_rk[256];
    __shared__ float sh_wkey[64], sh_erase[64], sh_wvec[64];
    __shared__ float sh_rstr[4], sh_free[4];
    __shared__ float sh_mraw[12], sh_modes[12];
    __shared__ float sh_scal[4];   // 0 wstr, 1 allocg, 2 writeg, 3 wwsum
    __shared__ float sh_alloc[256], sh_ww[256], sh_prec[256];
    __shared__ float red[256];
    __shared__ float sv[256];
    __shared__ int   si[256];
    __shared__ float sc[256];
    __shared__ float stage[4][4][256];   // [row-group][r][col]
    __shared__ float bws[4][256], fws[4][256], crs[4][256], wsn[4][256];

    int b = blockIdx.x;
    int tid = threadIdx.x;

#pragma unroll
    for (int r = 0; r < 4; r++)
        wro[r][tid] = g_state[OFF_WR + b * 1024 + r * 256 + tid];
    sh_prec[tid] = g_state[OFF_PREC + b * 256 + tid];

    // ---- Phase A: xi reduce + interface transforms ----
    for (int t = tid; t < IFTOT; t += 256) {
        float v = bif[t];
        for (int z = 0; z < 4; z++)
            v += g_part[XIP + (size_t)z * XISTRIDE + b * IFTOT + t];
        if (t < 256)       sh_rk[t] = tanhf(v);
        else if (t < 260)  sh_rstr[t - 256] = softplusf(v);
        else if (t < 324)  sh_wkey[t - 260] = tanhf(v);
        else if (t == 324) sh_scal[0] = softplusf(v);
        else if (t < 389)  sh_erase[t - 325] = sigf(v);
        else if (t < 453)  sh_wvec[t - 389] = tanhf(v);
        else if (t < 457)  sh_free[t - 453] = sigf(v);
        else if (t == 457) sh_scal[1] = sigf(v);
        else if (t == 458) sh_scal[2] = sigf(v);
        else               sh_mraw[t - 459] = v;
    }
    __syncthreads();
    if (tid < 4) {
        float v0 = sh_mraw[tid * 3], v1 = sh_mraw[tid * 3 + 1], v2 = sh_mraw[tid * 3 + 2];
        float m = fmaxf(v0, fmaxf(v1, v2));
        float e0 = expf(v0 - m), e1 = expf(v1 - m), e2 = expf(v2 - m);
        float s = e0 + e1 + e2;
        sh_modes[tid * 3] = e0 / s;
        sh_modes[tid * 3 + 1] = e1 / s;
        sh_modes[tid * 3 + 2] = e2 / s;
    }
    __syncthreads();

    // ---- Phase B: usage update + stable argsort + alloc ----
    float psi = 1.0f;
#pragma unroll
    for (int r = 0; r < 4; r++)
        psi *= 1.0f - sh_free[r] * wro[r][tid];
    float uo = g_state[OFF_USAGE + b * 256 + tid];
    float wo = g_state[OFF_WW + b * 256 + tid];
    float u = (uo + wo - uo * wo) * psi;
    g_state[OFF_USAGE + b * 256 + tid] = u;
    sv[tid] = u; si[tid] = tid;
    __syncthreads();
    for (int k = 2; k <= 256; k <<= 1) {
        for (int j = k >> 1; j > 0; j >>= 1) {
            int ixj = tid ^ j;
            if (ixj > tid) {
                float v1 = sv[tid], v2 = sv[ixj];
                int i1 = si[tid], i2 = si[ixj];
                bool up = ((tid & k) == 0);
                bool gt = (v1 > v2) || (v1 == v2 && i1 > i2);
                bool doswap = up ? gt : !gt;
                if (doswap) { sv[tid] = v2; sv[ixj] = v1; si[tid] = i2; si[ixj] = i1; }
            }
            __syncthreads();
        }
    }
    sc[tid] = sv[tid];
    __syncthreads();
    for (int off = 1; off < 256; off <<= 1) {
        float tval = (tid >= off) ? sc[tid - off] : 1.0f;
        __syncthreads();
        sc[tid] *= tval;
        __syncthreads();
    }
    float cpe = (tid == 0) ? 1.0f : sc[tid - 1];
    sh_alloc[si[tid]] = (1.0f - sv[tid]) * cpe;
    __syncthreads();

    // ---- Phase C: write content weights + ww + wwsum (OLD mem) ----
    float kn = 0;
#pragma unroll 8
    for (int w = 0; w < 64; w++) kn += sh_wkey[w] * sh_wkey[w];
    kn = sqrtf(kn) + EPSV;
    float dot = 0, mn0 = 0;
    size_t mbase = (size_t)OFF_MEM + (size_t)b * NN * WW;
#pragma unroll 8
    for (int w = 0; w < 64; w++) {
        float m = g_state[mbase + (size_t)tid * WW + w];
        dot += m * sh_wkey[w];
        mn0 += m * m;
    }
    float sim = sh_scal[0] * dot / ((sqrtf(mn0) + EPSV) * kn);
    float mx = blk_max(sim, red, tid);
    float e = expf(sim - mx);
    float sm = blk_sum(e, red, tid);
    float cwv = e / sm;
    float ag = sh_scal[1], wg = sh_scal[2];
    float wwv = wg * (ag * sh_alloc[tid] + (1.0f - ag) * cwv);
    sh_ww[tid] = wwv;
    g_state[OFF_WW + b * 256 + tid] = wwv;
    float wws = blk_sum(wwv, red, tid);
    if (tid == 0) sh_scal[3] = wws;
    __syncthreads();

    // ---- Phase D: memory update (float4) ----
    for (int i = tid * 4; i < NN * WW; i += 1024) {
        float4 m = *(const float4*)&g_state[mbase + i];
        int n = i >> 6, w = i & 63;
        float wwn = sh_ww[n];
        m.x = m.x * (1.0f - wwn * sh_erase[w])     + wwn * sh_wvec[w];
        m.y = m.y * (1.0f - wwn * sh_erase[w + 1]) + wwn * sh_wvec[w + 1];
        m.z = m.z * (1.0f - wwn * sh_erase[w + 2]) + wwn * sh_wvec[w + 2];
        m.w = m.w * (1.0f - wwn * sh_erase[w + 3]) + wwn * sh_wvec[w + 3];
        *(float4*)&g_state[mbase + i] = m;
    }

    // ---- Phase E: link update (float4) + staged bw + prec ----
    {
        int cg = tid & 63;          // column group (4 cols)
        int pr = tid >> 6;          // row group (64 rows)
        int j0 = cg * 4;
        size_t lb = (size_t)OFF_LINK + (size_t)b * 65536;
        float wwj0 = sh_ww[j0],     wwj1 = sh_ww[j0 + 1];
        float wwj2 = sh_ww[j0 + 2], wwj3 = sh_ww[j0 + 3];
        float pj0 = sh_prec[j0],     pj1 = sh_prec[j0 + 1];
        float pj2 = sh_prec[j0 + 2], pj3 = sh_prec[j0 + 3];
        float bwa[4][4] = {};
        int pend = pr * 64 + 64;
#pragma unroll 2
        for (int p = pr * 64; p < pend; p++) {
            float4 l = *(const float4*)&g_state[lb + (size_t)p * 256 + j0];
            float wi = sh_ww[p];
            float f = 1.0f - wi;
            float4 ln;
            ln.x = (p == j0)     ? 0.0f : (f - wwj0) * l.x + wi * pj0;
            ln.y = (p == j0 + 1) ? 0.0f : (f - wwj1) * l.y + wi * pj1;
            ln.z = (p == j0 + 2) ? 0.0f : (f - wwj2) * l.z + wi * pj2;
            ln.w = (p == j0 + 3) ? 0.0f : (f - wwj3) * l.w + wi * pj3;
            *(float4*)&g_state[lb + (size_t)p * 256 + j0] = ln;
#pragma unroll
            for (int r = 0; r < 4; r++) {
                float w = wro[r][p];
                bwa[r][0] += ln.x * w; bwa[r][1] += ln.y * w;
                bwa[r][2] += ln.z * w; bwa[r][3] += ln.w * w;
            }
        }
#pragma unroll
        for (int r = 0; r < 4; r++) {
            stage[pr][r][j0]     = bwa[r][0];
            stage[pr][r][j0 + 1] = bwa[r][1];
            stage[pr][r][j0 + 2] = bwa[r][2];
            stage[pr][r][j0 + 3] = bwa[r][3];
        }
        g_state[OFF_PREC + b * 256 + tid] = (1.0f - sh_scal[3]) * sh_prec[tid] + sh_ww[tid];
    }
    __syncthreads();
#pragma unroll
    for (int r = 0; r < 4; r++)
        bws[r][tid] = stage[0][r][tid] + stage[1][r][tid] + stage[2][r][tid] + stage[3][r][tid];

    // ---- Phase F: fw (new link, old wr), float4 ----
    {
        int warp = tid >> 5, lane = tid & 31;
        size_t lb = (size_t)OFF_LINK + (size_t)b * 65536;
        int j0 = lane * 8;
        for (int i = warp * 32; i < warp * 32 + 32; i++) {
            float4 la = *(const float4*)&g_state[lb + (size_t)i * 256 + j0];
            float4 lc = *(const float4*)&g_state[lb + (size_t)i * 256 + j0 + 4];
            float acc[4];
#pragma unroll
            for (int r = 0; r < 4; r++) {
                acc[r] = la.x * wro[r][j0]     + la.y * wro[r][j0 + 1]
                       + la.z * wro[r][j0 + 2] + la.w * wro[r][j0 + 3]
                       + lc.x * wro[r][j0 + 4] + lc.y * wro[r][j0 + 5]
                       + lc.z * wro[r][j0 + 6] + lc.w * wro[r][j0 + 7];
            }
#pragma unroll
            for (int r = 0; r < 4; r++) {
#pragma unroll
                for (int off = 16; off > 0; off >>= 1)
                    acc[r] += __shfl_xor_sync(0xffffffff, acc[r], off);
            }
            if (lane == 0) {
#pragma unroll
                for (int r = 0; r < 4; r++) fws[r][i] = acc[r];
            }
        }
    }
    __syncthreads();

    // ---- Phase G: read content weights (NEW mem) ----
    float kn2[4];
#pragma unroll
    for (int r = 0; r < 4; r++) {
        float s = 0;
#pragma unroll 8
        for (int w = 0; w < 64; w++) s += sh_rk[r * 64 + w] * sh_rk[r * 64 + w];
        kn2[r] = sqrtf(s) + EPSV;
    }
    float mn = 0;
    float dots[4] = {0, 0, 0, 0};
#pragma unroll 4
    for (int w = 0; w < 64; w++) {
        float m = g_state[mbase + (size_t)tid * WW + w];
        mn += m * m;
#pragma unroll
        for (int r = 0; r < 4; r++) dots[r] += m * sh_rk[r * 64 + w];
    }
    float mnorm = sqrtf(mn) + EPSV;
    for (int r = 0; r < 4; r++) {
        float simr = sh_rstr[r] * dots[r] / (mnorm * kn2[r]);
        float mxr = blk_max(simr, red, tid);
        float er = expf(simr - mxr);
        float smr = blk_sum(er, red, tid);
        crs[r][tid] = er / smr;
    }

    // ---- Phase H: wr update + rvec ----
#pragma unroll
    for (int r = 0; r < 4; r++) {
        float v = sh_modes[r * 3 + 0] * bws[r][tid]
                + sh_modes[r * 3 + 1] * crs[r][tid]
                + sh_modes[r * 3 + 2] * fws[r][tid];
        wsn[r][tid] = v;
        g_state[OFF_WR + b * 1024 + r * 256 + tid] = v;
    }
    __syncthreads();
    {
        int r2 = tid >> 6;
        int w = tid & 63;
        float acc = 0;
#pragma unroll 4
        for (int n = 0; n < 256; n++)
            acc += wsn[r2][n] * g_state[mbase + (size_t)n * 64 + w];
        g_state[OFF_RVEC + b * 256 + tid] = acc;
    }
}

// ---------------- host ----------------
static void dnc_step(float* S, float* part, float* outb, float* qsum,
                     int use_pre, int t, const float* cin, float* cout_,
                     const float* Wih_rvec_or_full, int is_controller, const float* comb,
                     const float* Wih, const float* Whh, const float* bgate,
                     const float* Wif, const float* bif,
                     const float* Wout, const float* bout) {
    SegP gp = {};
    int ng;
    if (!is_controller) {
        // gates: rvec 2x128 + h 4x128 = 6 segments
        for (int u = 0; u < 2; u++) {
            gp.A[u] = S + OFF_RVEC + u * 128;
            gp.W[u] = Wih + (size_t)(EE + u * 128) * 2048;
            gp.K[u] = 128; gp.lda[u] = 256;
        }
        for (int u = 0; u < 4; u++) {
            gp.A[2 + u] = S + OFF_H + u * 128;
            gp.W[2 + u] = Whh + (size_t)(u * 128) * 2048;
            gp.K[2 + u] = 128; gp.lda[2 + u] = 512;
        }
        ng = 6;
    } else {
        // gates: comb 4x256 + rvec 1x256 + h 2x256 = 7 segments
        for (int u = 0; u < 4; u++) {
            gp.A[u] = comb + u * 256;
            gp.W[u] = Wih + (size_t)(u * 256) * 2048;
            gp.K[u] = 256; gp.lda[u] = 1024;
        }
        gp.A[4] = S + OFF_RVEC; gp.W[4] = Wih + (size_t)1024 * 2048; gp.K[4] = 256; gp.lda[4] = 256;
        for (int u = 0; u < 2; u++) {
            gp.A[5 + u] = S + OFF_H + u * 256;
            gp.W[5 + u] = Whh + (size_t)(u * 256) * 2048;
            gp.K[5 + u] = 256; gp.lda[5 + u] = 512;
        }
        ng = 7;
    }
    for (int u = 0; u < 8; u++) { gp.Nout[u] = 2048; gp.coff[u] = (long)u * GSTRIDE; }
    gemm64<<<dim3(32, 1, ng), 256>>>(gp, ng, part);

    k_xiout<<<dim3(16, 1, 8), 256>>>(Wif, Wout, bgate, ng, use_pre, t, cin, cout_);
    k_dnc<<<BB, 256>>>(bif);
    k_outfin<<<16, 256>>>(S + OFF_RVEC, Wout + (size_t)512 * CEE, bout, outb, qsum);
}

extern "C" void kernel_launch(void* const* d_in, const int* in_sizes, int n_in,
                              void* d_out, int out_size) {
    const float* img_feat = (const float*)d_in[0];
    const int*   qst      = (const int*)d_in[1];
    const float* emb      = (const float*)d_in[2];
    const float* img_W    = (const float*)d_in[3];
    const float* img_b    = (const float*)d_in[4];
    const float* q_Wih    = (const float*)d_in[5];
    const float* q_Whh    = (const float*)d_in[6];
    const float* q_b      = (const float*)d_in[7];
    const float* q_Wif    = (const float*)d_in[8];
    const float* q_bif    = (const float*)d_in[9];
    const float* q_Wout   = (const float*)d_in[10];
    const float* q_bout   = (const float*)d_in[11];
    const float* c_Wih    = (const float*)d_in[12];
    const float* c_Whh    = (const float*)d_in[13];
    const float* c_b      = (const float*)d_in[14];
    const float* c_Wif    = (const float*)d_in[15];
    const float* c_bif    = (const float*)d_in[16];
    const float* c_Wout   = (const float*)d_in[17];
    const float* c_bout   = (const float*)d_in[18];
    const float* fc1_W    = (const float*)d_in[19];
    const float* fc1_b    = (const float*)d_in[20];
    const float* fc2_W    = (const float*)d_in[21];
    const float* fc2_b    = (const float*)d_in[22];
    float* out = (float*)d_out;

    float *S, *cb, *qv, *pre, *part, *outb, *qsum, *comb, *last, *fc1;
    cudaGetSymbolAddress((void**)&S, g_state);
    cudaGetSymbolAddress((void**)&cb, g_cbuf);
    cudaGetSymbolAddress((void**)&qv, g_qv);
    cudaGetSymbolAddress((void**)&pre, g_pre);
    cudaGetSymbolAddress((void**)&part, g_part);
    cudaGetSymbolAddress((void**)&outb, g_outbuf);
    cudaGetSymbolAddress((void**)&qsum, g_qsum);
    cudaGetSymbolAddress((void**)&comb, g_comb);
    cudaGetSymbolAddress((void**)&last, g_last);
    cudaGetSymbolAddress((void**)&fc1, g_fc1);

    // zero state + c buffer + qsum
    k_zero<<<(STATE_TOT + 255) / 256, 256>>>(S, STATE_TOT);
    k_zero<<<(BB * HH + 255) / 256, 256>>>(cb, BB * HH);
    k_zero<<<(BB * CEE + 255) / 256, 256>>>(qsum, BB * CEE);

    // question embedding + hoisted x@Wih_x for all timesteps [1280 x 2048]
    k_embed<<<(BB * TT * EE + 255) / 256, 256>>>(qst, emb);
    {
        SegP pp = {};
        pp.A[0] = qv; pp.W[0] = q_Wih; pp.K[0] = EE; pp.lda[0] = EE;
        pp.Nout[0] = 2048; pp.coff[0] = 0;
        gemm64<<<dim3(32, (BB * TT) / 64, 1), 256>>>(pp, 1, pre);
    }

    // question DNC over T timesteps (c double-buffered by parity)
    for (int t = 0; t < TT; t++) {
        const float* cin = cb + (size_t)(t & 1) * BB * HH;
        float* cout_ = cb + (size_t)((t + 1) & 1) * BB * HH;
        dnc_step(S, part, outb, qsum, 1, t, cin, cout_,
                 0, 0, 0, q_Wih, q_Whh, q_b, q_Wif, q_bif, q_Wout, q_bout);
    }

    // image encoder (split-K 8) + combine
    {
        SegP ip = {};
        for (int z = 0; z < 8; z++) {
            ip.A[z] = img_feat + (size_t)z * 512;
            ip.W[z] = img_W + (size_t)z * 512 * CEE;
            ip.K[z] = 512;
            ip.lda[z] = 4096;
            ip.Nout[z] = 1024;
            ip.coff[z] = (long)z * 65536;
        }
        gemm64<<<dim3(16, 1, 8), 256>>>(ip, 8, part);
        k_comb<<<BB, 256>>>(img_b, 8);
    }

    // controller DNC (fresh state)
    k_zero<<<(STATE_TOT + 255) / 256, 256>>>(S, STATE_TOT);
    k_zero<<<(BB * HH + 255) / 256, 256>>>(cb, BB * HH);
    dnc_step(S, part, outb, 0, 0, 0, cb, cb + (size_t)BB * HH,
             0, 1, comb, c_Wih, c_Whh, c_b, c_Wif, c_bif, c_Wout, c_bout);

    // tail: last -> fc1(tanh) -> fc2
    k_last<<<(BB * (CEE + RWRW) + 255) / 256, 256>>>();
    {
        SegP f1 = {};
        for (int z = 0; z < 8; z++) {
            f1.A[z] = last + (size_t)z * 160;
            f1.W[z] = fc1_W + (size_t)z * 160 * ANSN;
            f1.K[z] = 160;
            f1.lda[z] = CEE + RWRW;
            f1.Nout[z] = ANSN;
            f1.coff[z] = (long)z * 64 * ANSN;
        }
        gemm64<<<dim3(47, 1, 8), 256>>>(f1, 8, part);
        k_red<<<(64 * ANSN + 255) / 256, 256>>>(8, ANSN, fc1_b, fc1, 2);
    }
    {
        SegP f2 = {};
        for (int z = 0; z < 8; z++) {
            f2.A[z] = fc1 + (size_t)z * 375;
            f2.W[z] = fc2_W + (size_t)z * 375 * ANSN;
            f2.K[z] = 375;
            f2.lda[z] = ANSN;
            f2.Nout[z] = ANSN;
            f2.coff[z] = (long)z * 64 * ANSN;
        }
        gemm64<<<dim3(47, 1, 8), 256>>>(f2, 8, part);
        k_red<<<(64 * ANSN + 255) / 256, 256>>>(8, ANSN, fc2_b, out, 0);
    }
}

// round 9
// speedup vs baseline: 2.3071x; 2.3071x over previous
#include <cuda_runtime.h>
#include <math.h>
#include <stdint.h>

// ---------------- constants ----------------
#define BB 64
#define TT 20
#define EE 300
#define CEE 1024
#define ANSN 3000
#define HH 512
#define NN 256
#define WW 64
#define RR 4
#define RWRW 256
#define IFTOT 471
#define CLIPV 20.0f
#define EPSV 1e-6f

// state offsets inside g_state
#define OFF_MEM    0            // B*N*W
#define OFF_LINK   1048576      // B*N*N
#define OFF_PREC   5242880      // B*N
#define OFF_WR     5259264      // B*R*N
#define OFF_WW     5324800      // B*N
#define OFF_USAGE  5341184      // B*N
#define OFF_RVEC   5357568      // B*R*W
#define OFF_H      5373952      // B*H
#define OFF_C      5406720      // B*H
#define STATE_TOT  5439488

// g_part layout (floats)
#define GSTRIDE    131072       // 64*2048 gates partial stride (max 7 -> [0, 917504))
#define XIP        917504       // xi partials base (4 slices)
#define XISTRIDE   30144        // 64*471
#define OUTP       1048576      // out_hc partials base (4 slices)
#define OUTSTRIDE  65536        // 64*1024

// ---------------- device globals ----------------
__device__ __align__(16) float g_state[STATE_TOT];
__device__ __align__(16) float g_qv[BB * TT * EE];
__device__ __align__(16) float g_pre[BB * TT * 2048];
__device__ __align__(16) float g_part[8 * 64 * 3072];
__device__ __align__(16) float g_hc[BB * HH];
__device__ __align__(16) float g_outbuf[BB * CEE];
__device__ __align__(16) float g_qsum[BB * CEE];
__device__ __align__(16) float g_imgf[BB * CEE];
__device__ __align__(16) float g_comb[BB * CEE];
__device__ __align__(16) float g_last[BB * (CEE + RWRW)];
__device__ __align__(16) float g_fc1[BB * ANSN];

// ---------------- helpers ----------------
__device__ __forceinline__ float sigf(float x) { return 1.0f / (1.0f + expf(-x)); }
__device__ __forceinline__ float softplusf(float x) {
    return fmaxf(x, 0.0f) + log1pf(expf(-fabsf(x)));
}
__device__ __forceinline__ float blk_max(float v, volatile float* red, int tid) {
    red[tid] = v; __syncthreads();
    for (int s = 128; s > 0; s >>= 1) {
        if (tid < s) red[tid] = fmaxf((float)red[tid], (float)red[tid + s]);
        __syncthreads();
    }
    float r = red[0]; __syncthreads();
    return r;
}
__device__ __forceinline__ float blk_sum(float v, volatile float* red, int tid) {
    red[tid] = v; __syncthreads();
    for (int s = 128; s > 0; s >>= 1) {
        if (tid < s) red[tid] = (float)red[tid] + (float)red[tid + s];
        __syncthreads();
    }
    float r = red[0]; __syncthreads();
    return r;
}

// ---------------- misc kernels ----------------
__global__ void k_zero(float* p, int n) {
    int i = blockIdx.x * blockDim.x + threadIdx.x;
    if (i < n) p[i] = 0.0f;
}

__global__ void k_embed(const int* __restrict__ qst, const float* __restrict__ emb) {
    int i = blockIdx.x * blockDim.x + threadIdx.x;
    if (i >= BB * TT * EE) return;
    int e = i % EE;
    int bt = i / EE;
    int tok = qst[bt];
    g_qv[i] = tanhf(emb[(size_t)tok * EE + e]);
}

// ---------------- GEMM: 64x64 tile, 256 threads, 4x4 register blocking ----------------
struct SegP {
    const float* A[8];
    const float* W[8];
    int K[8];
    int lda[8];
    int Nout[8];
    long coff[8];          // partial output offset into Cout (split mode)
};

// gridDim.z>1: one segment per z, output to Cout + coff[z], width Nout[z]
// gridDim.z==1: loop all nseg segments, direct store to Cout (Nout[0])
__global__ void gemm64(SegP p, int nseg, float* __restrict__ Cout) {
    __shared__ __align__(16) float As[16][68];
    __shared__ __align__(16) float Ws[16][68];
    int tid = threadIdx.x;
    int tx = tid & 15;
    int ty = tid >> 4;
    int col0 = blockIdx.x * 64;
    int row0 = blockIdx.y * 64;
    float acc[4][4] = {};

    int z0, z1;
    if (gridDim.z > 1) { z0 = blockIdx.z; z1 = z0 + 1; } else { z0 = 0; z1 = nseg; }
    int Nout = p.Nout[z0];
    if (col0 >= Nout) return;
    bool nvec = ((Nout & 3) == 0);

    int lm = tid >> 2;            // A loader row 0..63
    int lkb = (tid & 3) * 4;      // A loader k offset
    int lkk = tid >> 4;           // W loader k 0..15
    int lnb = (tid & 15) * 4;     // W loader col offset

    for (int z = z0; z < z1; z++) {
        const float* A = p.A[z];
        const float* W = p.W[z];
        int K = p.K[z];
        int lda = p.lda[z];
        for (int k0 = 0; k0 < K; k0 += 16) {
            {
                const float* Ap = A + (size_t)(row0 + lm) * lda + k0 + lkb;
#pragma unroll
                for (int u = 0; u < 4; u++)
                    As[lkb + u][lm] = (k0 + lkb + u < K) ? Ap[u] : 0.0f;
            }
            {
                int kg = k0 + lkk;
                int c = col0 + lnb;
                if (nvec && kg < K && c + 3 < Nout) {
                    float4 v = *(const float4*)&W[(size_t)kg * Nout + c];
                    Ws[lkk][lnb] = v.x; Ws[lkk][lnb + 1] = v.y;
                    Ws[lkk][lnb + 2] = v.z; Ws[lkk][lnb + 3] = v.w;
                } else {
#pragma unroll
                    for (int u = 0; u < 4; u++)
                        Ws[lkk][lnb + u] = (kg < K && c + u < Nout)
                                           ? W[(size_t)kg * Nout + c + u] : 0.0f;
                }
            }
            __syncthreads();
#pragma unroll
            for (int kk = 0; kk < 16; kk++) {
                float4 a = *(const float4*)&As[kk][ty * 4];
                float4 w = *(const float4*)&Ws[kk][tx * 4];
                acc[0][0] += a.x * w.x; acc[0][1] += a.x * w.y;
                acc[0][2] += a.x * w.z; acc[0][3] += a.x * w.w;
                acc[1][0] += a.y * w.x; acc[1][1] += a.y * w.y;
                acc[1][2] += a.y * w.z; acc[1][3] += a.y * w.w;
                acc[2][0] += a.z * w.x; acc[2][1] += a.z * w.y;
                acc[2][2] += a.z * w.z; acc[2][3] += a.z * w.w;
                acc[3][0] += a.w * w.x; acc[3][1] += a.w * w.y;
                acc[3][2] += a.w * w.z; acc[3][3] += a.w * w.w;
            }
            __syncthreads();
        }
    }

    float* Cbase = Cout + ((gridDim.z > 1) ? p.coff[blockIdx.z] : 0);
#pragma unroll
    for (int i = 0; i < 4; i++) {
        int row = row0 + ty * 4 + i;
#pragma unroll
        for (int j = 0; j < 4; j++) {
            int c = col0 + tx * 4 + j;
            if (c < Nout)
                Cbase[(size_t)row * Nout + c] = acc[i][j];
        }
    }
}

// ---------------- LSTM (single pass) ----------------
__global__ void k_lstm(int nseg, int use_pre, int t, const float* __restrict__ bias) {
    int idx = blockIdx.x * blockDim.x + threadIdx.x;
    if (idx >= BB * HH) return;
    int b = idx >> 9;
    int j = idx & 511;
    float g[4];
#pragma unroll
    for (int q = 0; q < 4; q++) {
        int col = q * HH + j;
        float v = bias[col];
        if (use_pre) v += g_pre[((size_t)(b * TT + t)) * 2048 + col];
        for (int z = 0; z < nseg; z++) v += g_part[(size_t)z * GSTRIDE + b * 2048 + col];
        g[q] = v;
    }
    float cc = sigf(g[1]) * g_state[OFF_C + idx] + sigf(g[0]) * tanhf(g[2]);
    float hh = sigf(g[3]) * tanhf(cc);
    g_state[OFF_C + idx] = cc;
    g_state[OFF_H + idx] = hh;
    g_hc[idx] = fminf(fmaxf(hh, -CLIPV), CLIPV);
}

// ---------------- out-GEMM finish: rvec part + partials + bias + clip (+qsum) ----------------
__global__ void k_outfin(const float* __restrict__ A, const float* __restrict__ W,
                         const float* __restrict__ bias, float* __restrict__ outb,
                         float* __restrict__ qsum) {
    __shared__ __align__(16) float As[16][68];
    __shared__ __align__(16) float Ws[16][68];
    int tid = threadIdx.x;
    int tx = tid & 15, ty = tid >> 4;
    int col0 = blockIdx.x * 64;
    int lm = tid >> 2, lkb = (tid & 3) * 4;
    int lkk = tid >> 4, lnb = (tid & 15) * 4;
    float acc[4][4] = {};
    for (int k0 = 0; k0 < 256; k0 += 16) {
        {
            const float* Ap = A + (size_t)lm * 256 + k0 + lkb;
#pragma unroll
            for (int u = 0; u < 4; u++) As[lkb + u][lm] = Ap[u];
        }
        {
            float4 v = *(const float4*)&W[(size_t)(k0 + lkk) * CEE + col0 + lnb];
            Ws[lkk][lnb] = v.x; Ws[lkk][lnb + 1] = v.y;
            Ws[lkk][lnb + 2] = v.z; Ws[lkk][lnb + 3] = v.w;
        }
        __syncthreads();
#pragma unroll
        for (int kk = 0; kk < 16; kk++) {
            float4 a = *(const float4*)&As[kk][ty * 4];
            float4 w = *(const float4*)&Ws[kk][tx * 4];
            acc[0][0] += a.x * w.x; acc[0][1] += a.x * w.y;
            acc[0][2] += a.x * w.z; acc[0][3] += a.x * w.w;
            acc[1][0] += a.y * w.x; acc[1][1] += a.y * w.y;
            acc[1][2] += a.y * w.z; acc[1][3] += a.y * w.w;
            acc[2][0] += a.z * w.x; acc[2][1] += a.z * w.y;
            acc[2][2] += a.z * w.z; acc[2][3] += a.z * w.w;
            acc[3][0] += a.w * w.x; acc[3][1] += a.w * w.y;
            acc[3][2] += a.w * w.z; acc[3][3] += a.w * w.w;
        }
        __syncthreads();
    }
#pragma unroll
    for (int i = 0; i < 4; i++) {
        int row = ty * 4 + i;
#pragma unroll
        for (int j = 0; j < 4; j++) {
            int c = col0 + tx * 4 + j;
            float v = acc[i][j] + bias[c];
#pragma unroll
            for (int s2 = 0; s2 < 4; s2++)
                v += g_part[OUTP + (size_t)s2 * OUTSTRIDE + row * 1024 + c];
            v = fminf(fmaxf(v, -CLIPV), CLIPV);
            outb[row * 1024 + c] = v;
            if (qsum) qsum[row * 1024 + c] += v;
        }
    }
}

// ---------------- reduction / pointwise kernels ----------------
// act: 0 none, 2 tanh
__global__ void k_red(int nseg, int Nout, const float* __restrict__ bias,
                      float* __restrict__ out, int act) {
    int idx = blockIdx.x * blockDim.x + threadIdx.x;
    if (idx >= 64 * Nout) return;
    int j = idx % Nout;
    float v = bias[j];
    for (int z = 0; z < nseg; z++) v += g_part[(size_t)z * 64 * Nout + idx];
    if (act == 2) v = tanhf(v);
    out[idx] = v;
}

__global__ void k_comb(const float* __restrict__ img_b, int nseg) {
    __shared__ float red[256];
    int b = blockIdx.x;
    int tid = threadIdx.x;
    float s = 0;
    for (int j = tid; j < CEE; j += 256) {
        float v = img_b[j];
        for (int z = 0; z < nseg; z++) v += g_part[(size_t)z * 64 * 1024 + b * 1024 + j];
        g_imgf[b * CEE + j] = v;
        s += v * v;
    }
    float tot = blk_sum(s, red, tid);
    float inv = rsqrtf(tot);
    for (int j = tid; j < CEE; j += 256) {
        float v = g_imgf[b * CEE + j] * inv;
        g_comb[b * CEE + j] = tanhf(v * g_qsum[b * CEE + j] * (1.0f / (float)TT));
    }
}

__global__ void k_last() {
    int idx = blockIdx.x * blockDim.x + threadIdx.x;
    if (idx >= BB * (CEE + RWRW)) return;
    int b = idx / (CEE + RWRW);
    int j = idx % (CEE + RWRW);
    float v = (j < CEE) ? g_outbuf[b * CEE + j] : g_state[OFF_RVEC + b * 256 + (j - CEE)];
    g_last[idx] = tanhf(v);
}

// ---------------- fused per-batch DNC memory kernel ----------------
__global__ void k_dnc(const float* __restrict__ bif) {
    __shared__ float wro[4][256];
    __shared__ float sh_rk[256];
    __shared__ float sh_wkey[64], sh_erase[64], sh_wvec[64];
    __shared__ float sh_rstr[4], sh_free[4];
    __shared__ float sh_mraw[12], sh_modes[12];
    __shared__ float sh_scal[4];   // 0 wstr, 1 allocg, 2 writeg, 3 wwsum
    __shared__ float sh_alloc[256], sh_ww[256], sh_prec[256];
    __shared__ float red[256];
    __shared__ float sv[256];
    __shared__ int   si[256];
    __shared__ float sc[256];
    __shared__ float stage[4][4][256];   // [row-group][r][col]
    __shared__ float bws[4][256], fws[4][256], crs[4][256], wsn[4][256];

    int b = blockIdx.x;
    int tid = threadIdx.x;

#pragma unroll
    for (int r = 0; r < 4; r++)
        wro[r][tid] = g_state[OFF_WR + b * 1024 + r * 256 + tid];
    sh_prec[tid] = g_state[OFF_PREC + b * 256 + tid];

    // ---- Phase A: xi reduce + interface transforms ----
    for (int t = tid; t < IFTOT; t += 256) {
        float v = bif[t];
        for (int z = 0; z < 4; z++)
            v += g_part[XIP + (size_t)z * XISTRIDE + b * IFTOT + t];
        if (t < 256)       sh_rk[t] = tanhf(v);
        else if (t < 260)  sh_rstr[t - 256] = softplusf(v);
        else if (t < 324)  sh_wkey[t - 260] = tanhf(v);
        else if (t == 324) sh_scal[0] = softplusf(v);
        else if (t < 389)  sh_erase[t - 325] = sigf(v);
        else if (t < 453)  sh_wvec[t - 389] = tanhf(v);
        else if (t < 457)  sh_free[t - 453] = sigf(v);
        else if (t == 457) sh_scal[1] = sigf(v);
        else if (t == 458) sh_scal[2] = sigf(v);
        else               sh_mraw[t - 459] = v;
    }
    __syncthreads();
    if (tid < 4) {
        float v0 = sh_mraw[tid * 3], v1 = sh_mraw[tid * 3 + 1], v2 = sh_mraw[tid * 3 + 2];
        float m = fmaxf(v0, fmaxf(v1, v2));
        float e0 = expf(v0 - m), e1 = expf(v1 - m), e2 = expf(v2 - m);
        float s = e0 + e1 + e2;
        sh_modes[tid * 3] = e0 / s;
        sh_modes[tid * 3 + 1] = e1 / s;
        sh_modes[tid * 3 + 2] = e2 / s;
    }
    __syncthreads();

    // ---- Phase B: usage update + stable argsort + alloc ----
    float psi = 1.0f;
#pragma unroll
    for (int r = 0; r < 4; r++)
        psi *= 1.0f - sh_free[r] * wro[r][tid];
    float uo = g_state[OFF_USAGE + b * 256 + tid];
    float wo = g_state[OFF_WW + b * 256 + tid];
    float u = (uo + wo - uo * wo) * psi;
    g_state[OFF_USAGE + b * 256 + tid] = u;
    sv[tid] = u; si[tid] = tid;
    __syncthreads();
    for (int k = 2; k <= 256; k <<= 1) {
        for (int j = k >> 1; j > 0; j >>= 1) {
            int ixj = tid ^ j;
            if (ixj > tid) {
                float v1 = sv[tid], v2 = sv[ixj];
                int i1 = si[tid], i2 = si[ixj];
                bool up = ((tid & k) == 0);
                bool gt = (v1 > v2) || (v1 == v2 && i1 > i2);
                bool doswap = up ? gt : !gt;
                if (doswap) { sv[tid] = v2; sv[ixj] = v1; si[tid] = i2; si[ixj] = i1; }
            }
            __syncthreads();
        }
    }
    sc[tid] = sv[tid];
    __syncthreads();
    for (int off = 1; off < 256; off <<= 1) {
        float tval = (tid >= off) ? sc[tid - off] : 1.0f;
        __syncthreads();
        sc[tid] *= tval;
        __syncthreads();
    }
    float cpe = (tid == 0) ? 1.0f : sc[tid - 1];
    sh_alloc[si[tid]] = (1.0f - sv[tid]) * cpe;
    __syncthreads();

    // ---- Phase C: write content weights + ww + wwsum (OLD mem) ----
    float kn = 0;
#pragma unroll 8
    for (int w = 0; w < 64; w++) kn += sh_wkey[w] * sh_wkey[w];
    kn = sqrtf(kn) + EPSV;
    float dot = 0, mn0 = 0;
    size_t mbase = (size_t)OFF_MEM + (size_t)b * NN * WW;
#pragma unroll 8
    for (int w = 0; w < 64; w++) {
        float m = g_state[mbase + (size_t)tid * WW + w];
        dot += m * sh_wkey[w];
        mn0 += m * m;
    }
    float sim = sh_scal[0] * dot / ((sqrtf(mn0) + EPSV) * kn);
    float mx = blk_max(sim, red, tid);
    float e = expf(sim - mx);
    float sm = blk_sum(e, red, tid);
    float cwv = e / sm;
    float ag = sh_scal[1], wg = sh_scal[2];
    float wwv = wg * (ag * sh_alloc[tid] + (1.0f - ag) * cwv);
    sh_ww[tid] = wwv;
    g_state[OFF_WW + b * 256 + tid] = wwv;
    float wws = blk_sum(wwv, red, tid);
    if (tid == 0) sh_scal[3] = wws;
    __syncthreads();

    // ---- Phase D: memory update (float4) ----
    for (int i = tid * 4; i < NN * WW; i += 1024) {
        float4 m = *(const float4*)&g_state[mbase + i];
        int n = i >> 6, w = i & 63;
        float wwn = sh_ww[n];
        m.x = m.x * (1.0f - wwn * sh_erase[w])     + wwn * sh_wvec[w];
        m.y = m.y * (1.0f - wwn * sh_erase[w + 1]) + wwn * sh_wvec[w + 1];
        m.z = m.z * (1.0f - wwn * sh_erase[w + 2]) + wwn * sh_wvec[w + 2];
        m.w = m.w * (1.0f - wwn * sh_erase[w + 3]) + wwn * sh_wvec[w + 3];
        *(float4*)&g_state[mbase + i] = m;
    }

    // ---- Phase E: link update (float4) + staged bw + prec ----
    {
        int cg = tid & 63;          // column group (4 cols)
        int pr = tid >> 6;          // row group (64 rows)
        int j0 = cg * 4;
        size_t lb = (size_t)OFF_LINK + (size_t)b * 65536;
        float wwj0 = sh_ww[j0],     wwj1 = sh_ww[j0 + 1];
        float wwj2 = sh_ww[j0 + 2], wwj3 = sh_ww[j0 + 3];
        float pj0 = sh_prec[j0],     pj1 = sh_prec[j0 + 1];
        float pj2 = sh_prec[j0 + 2], pj3 = sh_prec[j0 + 3];
        float bwa[4][4] = {};
        int pend = pr * 64 + 64;
#pragma unroll 2
        for (int p = pr * 64; p < pend; p++) {
            float4 l = *(const float4*)&g_state[lb + (size_t)p * 256 + j0];
            float wi = sh_ww[p];
            float f = 1.0f - wi;
            float4 ln;
            ln.x = (p == j0)     ? 0.0f : (f - wwj0) * l.x + wi * pj0;
            ln.y = (p == j0 + 1) ? 0.0f : (f - wwj1) * l.y + wi * pj1;
            ln.z = (p == j0 + 2) ? 0.0f : (f - wwj2) * l.z + wi * pj2;
            ln.w = (p == j0 + 3) ? 0.0f : (f - wwj3) * l.w + wi * pj3;
            *(float4*)&g_state[lb + (size_t)p * 256 + j0] = ln;
#pragma unroll
            for (int r = 0; r < 4; r++) {
                float w = wro[r][p];
                bwa[r][0] += ln.x * w; bwa[r][1] += ln.y * w;
                bwa[r][2] += ln.z * w; bwa[r][3] += ln.w * w;
            }
        }
#pragma unroll
        for (int r = 0; r < 4; r++) {
            stage[pr][r][j0]     = bwa[r][0];
            stage[pr][r][j0 + 1] = bwa[r][1];
            stage[pr][r][j0 + 2] = bwa[r][2];
            stage[pr][r][j0 + 3] = bwa[r][3];
        }
        g_state[OFF_PREC + b * 256 + tid] = (1.0f - sh_scal[3]) * sh_prec[tid] + sh_ww[tid];
    }
    __syncthreads();
#pragma unroll
    for (int r = 0; r < 4; r++)
        bws[r][tid] = stage[0][r][tid] + stage[1][r][tid] + stage[2][r][tid] + stage[3][r][tid];

    // ---- Phase F: fw (new link, old wr), float4 ----
    {
        int warp = tid >> 5, lane = tid & 31;
        size_t lb = (size_t)OFF_LINK + (size_t)b * 65536;
        int j0 = lane * 8;
        for (int i = warp * 32; i < warp * 32 + 32; i++) {
            float4 la = *(const float4*)&g_state[lb + (size_t)i * 256 + j0];
            float4 lc = *(const float4*)&g_state[lb + (size_t)i * 256 + j0 + 4];
            float acc[4];
#pragma unroll
            for (int r = 0; r < 4; r++) {
                acc[r] = la.x * wro[r][j0]     + la.y * wro[r][j0 + 1]
                       + la.z * wro[r][j0 + 2] + la.w * wro[r][j0 + 3]
                       + lc.x * wro[r][j0 + 4] + lc.y * wro[r][j0 + 5]
                       + lc.z * wro[r][j0 + 6] + lc.w * wro[r][j0 + 7];
            }
#pragma unroll
            for (int r = 0; r < 4; r++) {
#pragma unroll
                for (int off = 16; off > 0; off >>= 1)
                    acc[r] += __shfl_xor_sync(0xffffffff, acc[r], off);
            }
            if (lane == 0) {
#pragma unroll
                for (int r = 0; r < 4; r++) fws[r][i] = acc[r];
            }
        }
    }
    __syncthreads();

    // ---- Phase G: read content weights (NEW mem) ----
    float kn2[4];
#pragma unroll
    for (int r = 0; r < 4; r++) {
        float s = 0;
#pragma unroll 8
        for (int w = 0; w < 64; w++) s += sh_rk[r * 64 + w] * sh_rk[r * 64 + w];
        kn2[r] = sqrtf(s) + EPSV;
    }
    float mn = 0;
    float dots[4] = {0, 0, 0, 0};
#pragma unroll 4
    for (int w = 0; w < 64; w++) {
        float m = g_state[mbase + (size_t)tid * WW + w];
        mn += m * m;
#pragma unroll
        for (int r = 0; r < 4; r++) dots[r] += m * sh_rk[r * 64 + w];
    }
    float mnorm = sqrtf(mn) + EPSV;
    for (int r = 0; r < 4; r++) {
        float simr = sh_rstr[r] * dots[r] / (mnorm * kn2[r]);
        float mxr = blk_max(simr, red, tid);
        float er = expf(simr - mxr);
        float smr = blk_sum(er, red, tid);
        crs[r][tid] = er / smr;
    }

    // ---- Phase H: wr update + rvec ----
#pragma unroll
    for (int r = 0; r < 4; r++) {
        float v = sh_modes[r * 3 + 0] * bws[r][tid]
                + sh_modes[r * 3 + 1] * crs[r][tid]
                + sh_modes[r * 3 + 2] * fws[r][tid];
        wsn[r][tid] = v;
        g_state[OFF_WR + b * 1024 + r * 256 + tid] = v;
    }
    __syncthreads();
    {
        int r2 = tid >> 6;
        int w = tid & 63;
        float acc = 0;
#pragma unroll 4
        for (int n = 0; n < 256; n++)
            acc += wsn[r2][n] * g_state[mbase + (size_t)n * 64 + w];
        g_state[OFF_RVEC + b * 256 + tid] = acc;
    }
}

// ---------------- host ----------------
static void dnc_step(float* S, float* hc, float* part, float* outb, float* qsum,
                     int use_pre, int t, int is_controller, const float* comb,
                     const float* Wih, const float* Whh, const float* bgate,
                     const float* Wif, const float* bif,
                     const float* Wout, const float* bout) {
    SegP gp = {};
    int ng;
    if (!is_controller) {
        // gates: rvec 2x128 + h 4x128 = 6 segments
        for (int u = 0; u < 2; u++) {
            gp.A[u] = S + OFF_RVEC + u * 128;
            gp.W[u] = Wih + (size_t)(EE + u * 128) * 2048;
            gp.K[u] = 128; gp.lda[u] = 256;
        }
        for (int u = 0; u < 4; u++) {
            gp.A[2 + u] = S + OFF_H + u * 128;
            gp.W[2 + u] = Whh + (size_t)(u * 128) * 2048;
            gp.K[2 + u] = 128; gp.lda[2 + u] = 512;
        }
        ng = 6;
    } else {
        // gates: comb 4x256 + rvec 1x256 + h 2x256 = 7 segments
        for (int u = 0; u < 4; u++) {
            gp.A[u] = comb + u * 256;
            gp.W[u] = Wih + (size_t)(u * 256) * 2048;
            gp.K[u] = 256; gp.lda[u] = 1024;
        }
        gp.A[4] = S + OFF_RVEC; gp.W[4] = Wih + (size_t)1024 * 2048; gp.K[4] = 256; gp.lda[4] = 256;
        for (int u = 0; u < 2; u++) {
            gp.A[5 + u] = S + OFF_H + u * 256;
            gp.W[5 + u] = Whh + (size_t)(u * 256) * 2048;
            gp.K[5 + u] = 256; gp.lda[5 + u] = 512;
        }
        ng = 7;
    }
    for (int u = 0; u < 8; u++) { gp.Nout[u] = 2048; gp.coff[u] = (long)u * GSTRIDE; }
    gemm64<<<dim3(32, 1, ng), 256>>>(gp, ng, part);

    k_lstm<<<(BB * HH + 255) / 256, 256>>>(ng, use_pre, t, bgate);

    // combined xi (z 0..3) + out_hc (z 4..7) GEMM, one launch
    SegP xo = {};
    for (int s = 0; s < 4; s++) {
        xo.A[s] = hc + s * 128;
        xo.W[s] = Wif + (size_t)(s * 128) * IFTOT;
        xo.K[s] = 128; xo.lda[s] = 512;
        xo.Nout[s] = IFTOT;
        xo.coff[s] = XIP + (long)s * XISTRIDE;
    }
    for (int s = 0; s < 4; s++) {
        xo.A[4 + s] = hc + s * 128;
        xo.W[4 + s] = Wout + (size_t)(s * 128) * CEE;
        xo.K[4 + s] = 128; xo.lda[4 + s] = 512;
        xo.Nout[4 + s] = CEE;
        xo.coff[4 + s] = OUTP + (long)s * OUTSTRIDE;
    }
    gemm64<<<dim3(16, 1, 8), 256>>>(xo, 8, part);

    k_dnc<<<BB, 256>>>(bif);
    k_outfin<<<16, 256>>>(S + OFF_RVEC, Wout + (size_t)512 * CEE, bout, outb, qsum);
}

extern "C" void kernel_launch(void* const* d_in, const int* in_sizes, int n_in,
                              void* d_out, int out_size) {
    const float* img_feat = (const float*)d_in[0];
    const int*   qst      = (const int*)d_in[1];
    const float* emb      = (const float*)d_in[2];
    const float* img_W    = (const float*)d_in[3];
    const float* img_b    = (const float*)d_in[4];
    const float* q_Wih    = (const float*)d_in[5];
    const float* q_Whh    = (const float*)d_in[6];
    const float* q_b      = (const float*)d_in[7];
    const float* q_Wif    = (const float*)d_in[8];
    const float* q_bif    = (const float*)d_in[9];
    const float* q_Wout   = (const float*)d_in[10];
    const float* q_bout   = (const float*)d_in[11];
    const float* c_Wih    = (const float*)d_in[12];
    const float* c_Whh    = (const float*)d_in[13];
    const float* c_b      = (const float*)d_in[14];
    const float* c_Wif    = (const float*)d_in[15];
    const float* c_bif    = (const float*)d_in[16];
    const float* c_Wout   = (const float*)d_in[17];
    const float* c_bout   = (const float*)d_in[18];
    const float* fc1_W    = (const float*)d_in[19];
    const float* fc1_b    = (const float*)d_in[20];
    const float* fc2_W    = (const float*)d_in[21];
    const float* fc2_b    = (const float*)d_in[22];
    float* out = (float*)d_out;

    float *S, *qv, *pre, *part, *hc, *outb, *qsum, *comb, *last, *fc1;
    cudaGetSymbolAddress((void**)&S, g_state);
    cudaGetSymbolAddress((void**)&qv, g_qv);
    cudaGetSymbolAddress((void**)&pre, g_pre);
    cudaGetSymbolAddress((void**)&part, g_part);
    cudaGetSymbolAddress((void**)&hc, g_hc);
    cudaGetSymbolAddress((void**)&outb, g_outbuf);
    cudaGetSymbolAddress((void**)&qsum, g_qsum);
    cudaGetSymbolAddress((void**)&comb, g_comb);
    cudaGetSymbolAddress((void**)&last, g_last);
    cudaGetSymbolAddress((void**)&fc1, g_fc1);

    // zero state + qsum
    k_zero<<<(STATE_TOT + 255) / 256, 256>>>(S, STATE_TOT);
    k_zero<<<(BB * CEE + 255) / 256, 256>>>(qsum, BB * CEE);

    // question embedding + hoisted x@Wih_x for all timesteps [1280 x 2048]
    k_embed<<<(BB * TT * EE + 255) / 256, 256>>>(qst, emb);
    {
        SegP pp = {};
        pp.A[0] = qv; pp.W[0] = q_Wih; pp.K[0] = EE; pp.lda[0] = EE;
        pp.Nout[0] = 2048; pp.coff[0] = 0;
        gemm64<<<dim3(32, (BB * TT) / 64, 1), 256>>>(pp, 1, pre);
    }

    // question DNC over T timesteps
    for (int t = 0; t < TT; t++)
        dnc_step(S, hc, part, outb, qsum, 1, t, 0, 0,
                 q_Wih, q_Whh, q_b, q_Wif, q_bif, q_Wout, q_bout);

    // image encoder (split-K 8) + combine
    {
        SegP ip = {};
        for (int z = 0; z < 8; z++) {
            ip.A[z] = img_feat + (size_t)z * 512;
            ip.W[z] = img_W + (size_t)z * 512 * CEE;
            ip.K[z] = 512;
            ip.lda[z] = 4096;
            ip.Nout[z] = 1024;
            ip.coff[z] = (long)z * 65536;
        }
        gemm64<<<dim3(16, 1, 8), 256>>>(ip, 8, part);
        k_comb<<<BB, 256>>>(img_b, 8);
    }

    // controller DNC (fresh state)
    k_zero<<<(STATE_TOT + 255) / 256, 256>>>(S, STATE_TOT);
    dnc_step(S, hc, part, outb, 0, 0, 0, 1, comb,
             c_Wih, c_Whh, c_b, c_Wif, c_bif, c_Wout, c_bout);

    // tail: last -> fc1(tanh) -> fc2
    k_last<<<(BB * (CEE + RWRW) + 255) / 256, 256>>>();
    {
        SegP f1 = {};
        for (int z = 0; z < 8; z++) {
            f1.A[z] = last + (size_t)z * 160;
            f1.W[z] = fc1_W + (size_t)z * 160 * ANSN;
            f1.K[z] = 160;
            f1.lda[z] = CEE + RWRW;
            f1.Nout[z] = ANSN;
            f1.coff[z] = (long)z * 64 * ANSN;
        }
        gemm64<<<dim3(47, 1, 8), 256>>>(f1, 8, part);
        k_red<<<(64 * ANSN + 255) / 256, 256>>>(8, ANSN, fc1_b, fc1, 2);
    }
    {
        SegP f2 = {};
        for (int z = 0; z < 8; z++) {
            f2.A[z] = fc1 + (size_t)z * 375;
            f2.W[z] = fc2_W + (size_t)z * 375 * ANSN;
            f2.K[z] = 375;
            f2.lda[z] = ANSN;
            f2.Nout[z] = ANSN;
            f2.coff[z] = (long)z * 64 * ANSN;
        }
        gemm64<<<dim3(47, 1, 8), 256>>>(f2, 8, part);
        k_red<<<(64 * ANSN + 255) / 256, 256>>>(8, ANSN, fc2_b, out, 0);
    }
}

// round 11
// speedup vs baseline: 2.5923x; 1.1236x over previous
#include <cuda_runtime.h>
#include <math.h>
#include <stdint.h>

// ---------------- constants ----------------
#define BB 64
#define TT 20
#define EE 300
#define CEE 1024
#define ANSN 3000
#define HH 512
#define NN 256
#define WW 64
#define RR 4
#define RWRW 256
#define IFTOT 471
#define CLIPV 20.0f
#define EPSV 1e-6f

// state offsets inside g_state
#define OFF_MEM    0            // B*N*W
#define OFF_LINK   1048576      // B*N*N
#define OFF_PREC   5242880      // B*N
#define OFF_WR     5259264      // B*R*N
#define OFF_WW     5324800      // B*N
#define OFF_USAGE  5341184      // B*N
#define OFF_RVEC   5357568      // B*R*W
#define OFF_H      5373952      // B*H
#define OFF_C      5406720      // B*H
#define STATE_TOT  5439488

// g_part layout (floats)
#define GSTRIDE    131072       // 64*2048 gates partial stride (max 7 -> [0, 917504))
#define XIP        917504       // xi partials base (4 slices)
#define XISTRIDE   30144        // 64*471

// ---------------- device globals ----------------
__device__ __align__(16) float g_state[STATE_TOT];
__device__ __align__(16) float g_qv[BB * TT * EE];
__device__ __align__(16) float g_pre[BB * TT * 2048];
__device__ __align__(16) float g_part[8 * 64 * 3072];
__device__ __align__(16) float g_hch[TT * BB * HH];     // hc history
__device__ __align__(16) float g_rvh[TT * BB * RWRW];   // rvec history
__device__ __align__(16) float g_outT[TT * BB * CEE];   // batched out-GEMM result
__device__ __align__(16) float g_outbuf[BB * CEE];
__device__ __align__(16) float g_qsum[BB * CEE];
__device__ __align__(16) float g_imgf[BB * CEE];
__device__ __align__(16) float g_comb[BB * CEE];
__device__ __align__(16) float g_last[BB * (CEE + RWRW)];
__device__ __align__(16) float g_fc1[BB * ANSN];

// ---------------- helpers ----------------
__device__ __forceinline__ float sigf(float x) { return 1.0f / (1.0f + expf(-x)); }
__device__ __forceinline__ float softplusf(float x) {
    return fmaxf(x, 0.0f) + log1pf(expf(-fabsf(x)));
}
__device__ __forceinline__ float blk_max(float v, volatile float* red, int tid) {
    red[tid] = v; __syncthreads();
    for (int s = 128; s > 0; s >>= 1) {
        if (tid < s) red[tid] = fmaxf((float)red[tid], (float)red[tid + s]);
        __syncthreads();
    }
    float r = red[0]; __syncthreads();
    return r;
}
__device__ __forceinline__ float blk_sum(float v, volatile float* red, int tid) {
    red[tid] = v; __syncthreads();
    for (int s = 128; s > 0; s >>= 1) {
        if (tid < s) red[tid] = (float)red[tid] + (float)red[tid + s];
        __syncthreads();
    }
    float r = red[0]; __syncthreads();
    return r;
}

// ---------------- misc kernels ----------------
__global__ void k_zero(float* p, int n) {
    int i = blockIdx.x * blockDim.x + threadIdx.x;
    if (i < n) p[i] = 0.0f;
}

__global__ void k_embed(const int* __restrict__ qst, const float* __restrict__ emb) {
    int i = blockIdx.x * blockDim.x + threadIdx.x;
    if (i >= BB * TT * EE) return;
    int e = i % EE;
    int bt = i / EE;
    int tok = qst[bt];
    g_qv[i] = tanhf(emb[(size_t)tok * EE + e]);
}

// ---------------- GEMM: 64x64 tile, 256 threads, 4x4 register blocking ----------------
struct SegP {
    const float* A[8];
    const float* W[8];
    int K[8];
    int lda[8];
    int Nout[8];
    long coff[8];          // partial output offset into Cout (split mode)
};

// gridDim.z>1: one segment per z, output to Cout + coff[z], width Nout[z]
// gridDim.z==1: loop all nseg segments, direct store to Cout (Nout[0]); rows via blockIdx.y
__global__ void gemm64(SegP p, int nseg, float* __restrict__ Cout) {
    __shared__ __align__(16) float As[16][68];
    __shared__ __align__(16) float Ws[16][68];
    int tid = threadIdx.x;
    int tx = tid & 15;
    int ty = tid >> 4;
    int col0 = blockIdx.x * 64;
    int row0 = blockIdx.y * 64;
    float acc[4][4] = {};

    int z0, z1;
    if (gridDim.z > 1) { z0 = blockIdx.z; z1 = z0 + 1; } else { z0 = 0; z1 = nseg; }
    int Nout = p.Nout[z0];
    if (col0 >= Nout) return;
    bool nvec = ((Nout & 3) == 0);

    int lm = tid >> 2;            // A loader row 0..63
    int lkb = (tid & 3) * 4;      // A loader k offset
    int lkk = tid >> 4;           // W loader k 0..15
    int lnb = (tid & 15) * 4;     // W loader col offset

    for (int z = z0; z < z1; z++) {
        const float* A = p.A[z];
        const float* W = p.W[z];
        int K = p.K[z];
        int lda = p.lda[z];
        for (int k0 = 0; k0 < K; k0 += 16) {
            {
                const float* Ap = A + (size_t)(row0 + lm) * lda + k0 + lkb;
#pragma unroll
                for (int u = 0; u < 4; u++)
                    As[lkb + u][lm] = (k0 + lkb + u < K) ? Ap[u] : 0.0f;
            }
            {
                int kg = k0 + lkk;
                int c = col0 + lnb;
                if (nvec && kg < K && c + 3 < Nout) {
                    float4 v = *(const float4*)&W[(size_t)kg * Nout + c];
                    Ws[lkk][lnb] = v.x; Ws[lkk][lnb + 1] = v.y;
                    Ws[lkk][lnb + 2] = v.z; Ws[lkk][lnb + 3] = v.w;
                } else {
#pragma unroll
                    for (int u = 0; u < 4; u++)
                        Ws[lkk][lnb + u] = (kg < K && c + u < Nout)
                                           ? W[(size_t)kg * Nout + c + u] : 0.0f;
                }
            }
            __syncthreads();
#pragma unroll
            for (int kk = 0; kk < 16; kk++) {
                float4 a = *(const float4*)&As[kk][ty * 4];
                float4 w = *(const float4*)&Ws[kk][tx * 4];
                acc[0][0] += a.x * w.x; acc[0][1] += a.x * w.y;
                acc[0][2] += a.x * w.z; acc[0][3] += a.x * w.w;
                acc[1][0] += a.y * w.x; acc[1][1] += a.y * w.y;
                acc[1][2] += a.y * w.z; acc[1][3] += a.y * w.w;
                acc[2][0] += a.z * w.x; acc[2][1] += a.z * w.y;
                acc[2][2] += a.z * w.z; acc[2][3] += a.z * w.w;
                acc[3][0] += a.w * w.x; acc[3][1] += a.w * w.y;
                acc[3][2] += a.w * w.z; acc[3][3] += a.w * w.w;
            }
            __syncthreads();
        }
    }

    float* Cbase = Cout + ((gridDim.z > 1) ? p.coff[blockIdx.z] : 0);
#pragma unroll
    for (int i = 0; i < 4; i++) {
        int row = row0 + ty * 4 + i;
#pragma unroll
        for (int j = 0; j < 4; j++) {
            int c = col0 + tx * 4 + j;
            if (c < Nout)
                Cbase[(size_t)row * Nout + c] = acc[i][j];
        }
    }
}

// ---------------- LSTM (single pass) ----------------
__global__ void k_lstm(int nseg, int use_pre, int t, const float* __restrict__ bias,
                       float* __restrict__ hc_out) {
    int idx = blockIdx.x * blockDim.x + threadIdx.x;
    if (idx >= BB * HH) return;
    int b = idx >> 9;
    int j = idx & 511;
    float g[4];
#pragma unroll
    for (int q = 0; q < 4; q++) {
        int col = q * HH + j;
        float v = bias[col];
        if (use_pre) v += g_pre[((size_t)(b * TT + t)) * 2048 + col];
        for (int z = 0; z < nseg; z++) v += g_part[(size_t)z * GSTRIDE + b * 2048 + col];
        g[q] = v;
    }
    float cc = sigf(g[1]) * g_state[OFF_C + idx] + sigf(g[0]) * tanhf(g[2]);
    float hh = sigf(g[3]) * tanhf(cc);
    g_state[OFF_C + idx] = cc;
    g_state[OFF_H + idx] = hh;
    hc_out[idx] = fminf(fmaxf(hh, -CLIPV), CLIPV);
}

// ---------------- batched out epilogue: qsum[b,c] = sum_t clip(outT + bias) ----------------
__global__ void k_qsum(const float* __restrict__ bias) {
    int idx = blockIdx.x * blockDim.x + threadIdx.x;
    if (idx >= BB * CEE) return;
    int b = idx >> 10;
    int c = idx & 1023;
    float bs = bias[c];
    float s = 0;
    for (int t = 0; t < TT; t++) {
        float v = g_outT[((size_t)t * BB + b) * CEE + c] + bs;
        s += fminf(fmaxf(v, -CLIPV), CLIPV);
    }
    g_qsum[idx] = s;
}

// controller out epilogue: outbuf = clip(outT0 + bias)
__global__ void k_ctrlout(const float* __restrict__ bias) {
    int idx = blockIdx.x * blockDim.x + threadIdx.x;
    if (idx >= BB * CEE) return;
    int c = idx & 1023;
    float v = g_outT[idx] + bias[c];
    g_outbuf[idx] = fminf(fmaxf(v, -CLIPV), CLIPV);
}

// ---------------- reduction / pointwise kernels ----------------
// act: 0 none, 2 tanh
__global__ void k_red(int nseg, int Nout, const float* __restrict__ bias,
                      float* __restrict__ out, int act) {
    int idx = blockIdx.x * blockDim.x + threadIdx.x;
    if (idx >= 64 * Nout) return;
    int j = idx % Nout;
    float v = bias[j];
    for (int z = 0; z < nseg; z++) v += g_part[(size_t)z * 64 * Nout + idx];
    if (act == 2) v = tanhf(v);
    out[idx] = v;
}

__global__ void k_comb(const float* __restrict__ img_b, int nseg) {
    __shared__ float red[256];
    int b = blockIdx.x;
    int tid = threadIdx.x;
    float s = 0;
    for (int j = tid; j < CEE; j += 256) {
        float v = img_b[j];
        for (int z = 0; z < nseg; z++) v += g_part[(size_t)z * 64 * 1024 + b * 1024 + j];
        g_imgf[b * CEE + j] = v;
        s += v * v;
    }
    float tot = blk_sum(s, red, tid);
    float inv = rsqrtf(tot);
    for (int j = tid; j < CEE; j += 256) {
        float v = g_imgf[b * CEE + j] * inv;
        g_comb[b * CEE + j] = tanhf(v * g_qsum[b * CEE + j] * (1.0f / (float)TT));
    }
}

__global__ void k_last() {
    int idx = blockIdx.x * blockDim.x + threadIdx.x;
    if (idx >= BB * (CEE + RWRW)) return;
    int b = idx / (CEE + RWRW);
    int j = idx % (CEE + RWRW);
    float v = (j < CEE) ? g_outbuf[b * CEE + j] : g_state[OFF_RVEC + b * 256 + (j - CEE)];
    g_last[idx] = tanhf(v);
}

// ---------------- fused per-batch DNC memory kernel ----------------
__global__ void k_dnc(const float* __restrict__ bif, float* __restrict__ rvh_slot) {
    __shared__ float wro[4][256];
    __shared__ float sh_rk[256];
    __shared__ float sh_wkey[64], sh_erase[64], sh_wvec[64];
    __shared__ float sh_rstr[4], sh_free[4];
    __shared__ float sh_mraw[12], sh_modes[12];
    __shared__ float sh_scal[4];   // 0 wstr, 1 allocg, 2 writeg, 3 wwsum
    __shared__ float sh_alloc[256], sh_ww[256], sh_prec[256];
    __shared__ float red[256];
    __shared__ float sv[256];
    __shared__ int   si[256];
    __shared__ float sc[256];
    __shared__ float stage[4][4][256];   // [row-group][r][col]
    __shared__ float bws[4][256], fws[4][256], crs[4][256], wsn[4][256];

    int b = blockIdx.x;
    int tid = threadIdx.x;

#pragma unroll
    for (int r = 0; r < 4; r++)
        wro[r][tid] = g_state[OFF_WR + b * 1024 + r * 256 + tid];
    sh_prec[tid] = g_state[OFF_PREC + b * 256 + tid];

    // ---- Phase A: xi reduce + interface transforms ----
    for (int t = tid; t < IFTOT; t += 256) {
        float v = bif[t];
        for (int z = 0; z < 4; z++)
            v += g_part[XIP + (size_t)z * XISTRIDE + b * IFTOT + t];
        if (t < 256)       sh_rk[t] = tanhf(v);
        else if (t < 260)  sh_rstr[t - 256] = softplusf(v);
        else if (t < 324)  sh_wkey[t - 260] = tanhf(v);
        else if (t == 324) sh_scal[0] = softplusf(v);
        else if (t < 389)  sh_erase[t - 325] = sigf(v);
        else if (t < 453)  sh_wvec[t - 389] = tanhf(v);
        else if (t < 457)  sh_free[t - 453] = sigf(v);
        else if (t == 457) sh_scal[1] = sigf(v);
        else if (t == 458) sh_scal[2] = sigf(v);
        else               sh_mraw[t - 459] = v;
    }
    __syncthreads();
    if (tid < 4) {
        float v0 = sh_mraw[tid * 3], v1 = sh_mraw[tid * 3 + 1], v2 = sh_mraw[tid * 3 + 2];
        float m = fmaxf(v0, fmaxf(v1, v2));
        float e0 = expf(v0 - m), e1 = expf(v1 - m), e2 = expf(v2 - m);
        float s = e0 + e1 + e2;
        sh_modes[tid * 3] = e0 / s;
        sh_modes[tid * 3 + 1] = e1 / s;
        sh_modes[tid * 3 + 2] = e2 / s;
    }
    __syncthreads();

    // ---- Phase B: usage update + stable argsort + alloc ----
    float psi = 1.0f;
#pragma unroll
    for (int r = 0; r < 4; r++)
        psi *= 1.0f - sh_free[r] * wro[r][tid];
    float uo = g_state[OFF_USAGE + b * 256 + tid];
    float wo = g_state[OFF_WW + b * 256 + tid];
    float u = (uo + wo - uo * wo) * psi;
    g_state[OFF_USAGE + b * 256 + tid] = u;
    sv[tid] = u; si[tid] = tid;
    __syncthreads();
    for (int k = 2; k <= 256; k <<= 1) {
        for (int j = k >> 1; j > 0; j >>= 1) {
            int ixj = tid ^ j;
            if (ixj > tid) {
                float v1 = sv[tid], v2 = sv[ixj];
                int i1 = si[tid], i2 = si[ixj];
                bool up = ((tid & k) == 0);
                bool gt = (v1 > v2) || (v1 == v2 && i1 > i2);
                bool doswap = up ? gt : !gt;
                if (doswap) { sv[tid] = v2; sv[ixj] = v1; si[tid] = i2; si[ixj] = i1; }
            }
            __syncthreads();
        }
    }
    sc[tid] = sv[tid];
    __syncthreads();
    for (int off = 1; off < 256; off <<= 1) {
        float tval = (tid >= off) ? sc[tid - off] : 1.0f;
        __syncthreads();
        sc[tid] *= tval;
        __syncthreads();
    }
    float cpe = (tid == 0) ? 1.0f : sc[tid - 1];
    sh_alloc[si[tid]] = (1.0f - sv[tid]) * cpe;
    __syncthreads();

    // ---- Phase C: write content weights + ww + wwsum (OLD mem) ----
    float kn = 0;
#pragma unroll 8
    for (int w = 0; w < 64; w++) kn += sh_wkey[w] * sh_wkey[w];
    kn = sqrtf(kn) + EPSV;
    float dot = 0, mn0 = 0;
    size_t mbase = (size_t)OFF_MEM + (size_t)b * NN * WW;
#pragma unroll 8
    for (int w = 0; w < 64; w++) {
        float m = g_state[mbase + (size_t)tid * WW + w];
        dot += m * sh_wkey[w];
        mn0 += m * m;
    }
    float sim = sh_scal[0] * dot / ((sqrtf(mn0) + EPSV) * kn);
    float mx = blk_max(sim, red, tid);
    float e = expf(sim - mx);
    float sm = blk_sum(e, red, tid);
    float cwv = e / sm;
    float ag = sh_scal[1], wg = sh_scal[2];
    float wwv = wg * (ag * sh_alloc[tid] + (1.0f - ag) * cwv);
    sh_ww[tid] = wwv;
    g_state[OFF_WW + b * 256 + tid] = wwv;
    float wws = blk_sum(wwv, red, tid);
    if (tid == 0) sh_scal[3] = wws;
    __syncthreads();

    // ---- Phase D: memory update (float4) ----
    for (int i = tid * 4; i < NN * WW; i += 1024) {
        float4 m = *(const float4*)&g_state[mbase + i];
        int n = i >> 6, w = i & 63;
        float wwn = sh_ww[n];
        m.x = m.x * (1.0f - wwn * sh_erase[w])     + wwn * sh_wvec[w];
        m.y = m.y * (1.0f - wwn * sh_erase[w + 1]) + wwn * sh_wvec[w + 1];
        m.z = m.z * (1.0f - wwn * sh_erase[w + 2]) + wwn * sh_wvec[w + 2];
        m.w = m.w * (1.0f - wwn * sh_erase[w + 3]) + wwn * sh_wvec[w + 3];
        *(float4*)&g_state[mbase + i] = m;
    }

    // ---- Phase E: link update (float4) + staged bw + prec ----
    {
        int cg = tid & 63;          // column group (4 cols)
        int pr = tid >> 6;          // row group (64 rows)
        int j0 = cg * 4;
        size_t lb = (size_t)OFF_LINK + (size_t)b * 65536;
        float wwj0 = sh_ww[j0],     wwj1 = sh_ww[j0 + 1];
        float wwj2 = sh_ww[j0 + 2], wwj3 = sh_ww[j0 + 3];
        float pj0 = sh_prec[j0],     pj1 = sh_prec[j0 + 1];
        float pj2 = sh_prec[j0 + 2], pj3 = sh_prec[j0 + 3];
        float bwa[4][4] = {};
        int pend = pr * 64 + 64;
#pragma unroll 2
        for (int p = pr * 64; p < pend; p++) {
            float4 l = *(const float4*)&g_state[lb + (size_t)p * 256 + j0];
            float wi = sh_ww[p];
            float f = 1.0f - wi;
            float4 ln;
            ln.x = (p == j0)     ? 0.0f : (f - wwj0) * l.x + wi * pj0;
            ln.y = (p == j0 + 1) ? 0.0f : (f - wwj1) * l.y + wi * pj1;
            ln.z = (p == j0 + 2) ? 0.0f : (f - wwj2) * l.z + wi * pj2;
            ln.w = (p == j0 + 3) ? 0.0f : (f - wwj3) * l.w + wi * pj3;
            *(float4*)&g_state[lb + (size_t)p * 256 + j0] = ln;
#pragma unroll
            for (int r = 0; r < 4; r++) {
                float w = wro[r][p];
                bwa[r][0] += ln.x * w; bwa[r][1] += ln.y * w;
                bwa[r][2] += ln.z * w; bwa[r][3] += ln.w * w;
            }
        }
#pragma unroll
        for (int r = 0; r < 4; r++) {
            stage[pr][r][j0]     = bwa[r][0];
            stage[pr][r][j0 + 1] = bwa[r][1];
            stage[pr][r][j0 + 2] = bwa[r][2];
            stage[pr][r][j0 + 3] = bwa[r][3];
        }
        g_state[OFF_PREC + b * 256 + tid] = (1.0f - sh_scal[3]) * sh_prec[tid] + sh_ww[tid];
    }
    __syncthreads();
#pragma unroll
    for (int r = 0; r < 4; r++)
        bws[r][tid] = stage[0][r][tid] + stage[1][r][tid] + stage[2][r][tid] + stage[3][r][tid];

    // ---- Phase F: fw (new link, old wr), float4 ----
    {
        int warp = tid >> 5, lane = tid & 31;
        size_t lb = (size_t)OFF_LINK + (size_t)b * 65536;
        int j0 = lane * 8;
        for (int i = warp * 32; i < warp * 32 + 32; i++) {
            float4 la = *(const float4*)&g_state[lb + (size_t)i * 256 + j0];
            float4 lc = *(const float4*)&g_state[lb + (size_t)i * 256 + j0 + 4];
            float acc[4];
#pragma unroll
            for (int r = 0; r < 4; r++) {
                acc[r] = la.x * wro[r][j0]     + la.y * wro[r][j0 + 1]
                       + la.z * wro[r][j0 + 2] + la.w * wro[r][j0 + 3]
                       + lc.x * wro[r][j0 + 4] + lc.y * wro[r][j0 + 5]
                       + lc.z * wro[r][j0 + 6] + lc.w * wro[r][j0 + 7];
            }
#pragma unroll
            for (int r = 0; r < 4; r++) {
#pragma unroll
                for (int off = 16; off > 0; off >>= 1)
                    acc[r] += __shfl_xor_sync(0xffffffff, acc[r], off);
            }
            if (lane == 0) {
#pragma unroll
                for (int r = 0; r < 4; r++) fws[r][i] = acc[r];
            }
        }
    }
    __syncthreads();

    // ---- Phase G: read content weights (NEW mem) ----
    float kn2[4];
#pragma unroll
    for (int r = 0; r < 4; r++) {
        float s = 0;
#pragma unroll 8
        for (int w = 0; w < 64; w++) s += sh_rk[r * 64 + w] * sh_rk[r * 64 + w];
        kn2[r] = sqrtf(s) + EPSV;
    }
    float mn = 0;
    float dots[4] = {0, 0, 0, 0};
#pragma unroll 4
    for (int w = 0; w < 64; w++) {
        float m = g_state[mbase + (size_t)tid * WW + w];
        mn += m * m;
#pragma unroll
        for (int r = 0; r < 4; r++) dots[r] += m * sh_rk[r * 64 + w];
    }
    float mnorm = sqrtf(mn) + EPSV;
    for (int r = 0; r < 4; r++) {
        float simr = sh_rstr[r] * dots[r] / (mnorm * kn2[r]);
        float mxr = blk_max(simr, red, tid);
        float er = expf(simr - mxr);
        float smr = blk_sum(er, red, tid);
        crs[r][tid] = er / smr;
    }

    // ---- Phase H: wr update + rvec ----
#pragma unroll
    for (int r = 0; r < 4; r++) {
        float v = sh_modes[r * 3 + 0] * bws[r][tid]
                + sh_modes[r * 3 + 1] * crs[r][tid]
                + sh_modes[r * 3 + 2] * fws[r][tid];
        wsn[r][tid] = v;
        g_state[OFF_WR + b * 1024 + r * 256 + tid] = v;
    }
    __syncthreads();
    {
        int r2 = tid >> 6;
        int w = tid & 63;
        float acc = 0;
#pragma unroll 4
        for (int n = 0; n < 256; n++)
            acc += wsn[r2][n] * g_state[mbase + (size_t)n * 64 + w];
        g_state[OFF_RVEC + b * 256 + tid] = acc;
        rvh_slot[b * 256 + tid] = acc;
    }
}

// ---------------- host ----------------
// One DNC recurrence step: 4 launches (gates, lstm, xi, dnc).
static void dnc_step(float* S, float* part, float* hch_slot, float* rvh_slot,
                     int use_pre, int t, int is_controller, const float* comb,
                     const float* Wih, const float* Whh, const float* bgate,
                     const float* Wif, const float* bif) {
    SegP gp = {};
    int ng;
    if (!is_controller) {
        // gates: rvec 2x128 + h 4x128 = 6 segments
        for (int u = 0; u < 2; u++) {
            gp.A[u] = S + OFF_RVEC + u * 128;
            gp.W[u] = Wih + (size_t)(EE + u * 128) * 2048;
            gp.K[u] = 128; gp.lda[u] = 256;
        }
        for (int u = 0; u < 4; u++) {
            gp.A[2 + u] = S + OFF_H + u * 128;
            gp.W[2 + u] = Whh + (size_t)(u * 128) * 2048;
            gp.K[2 + u] = 128; gp.lda[2 + u] = 512;
        }
        ng = 6;
    } else {
        // gates: comb 4x256 + rvec 1x256 + h 2x256 = 7 segments
        for (int u = 0; u < 4; u++) {
            gp.A[u] = comb + u * 256;
            gp.W[u] = Wih + (size_t)(u * 256) * 2048;
            gp.K[u] = 256; gp.lda[u] = 1024;
        }
        gp.A[4] = S + OFF_RVEC; gp.W[4] = Wih + (size_t)1024 * 2048; gp.K[4] = 256; gp.lda[4] = 256;
        for (int u = 0; u < 2; u++) {
            gp.A[5 + u] = S + OFF_H + u * 256;
            gp.W[5 + u] = Whh + (size_t)(u * 256) * 2048;
            gp.K[5 + u] = 256; gp.lda[5 + u] = 512;
        }
        ng = 7;
    }
    for (int u = 0; u < 8; u++) { gp.Nout[u] = 2048; gp.coff[u] = (long)u * GSTRIDE; }
    gemm64<<<dim3(32, 1, ng), 256>>>(gp, ng, part);

    k_lstm<<<(BB * HH + 255) / 256, 256>>>(ng, use_pre, t, bgate, hch_slot);

    // xi GEMM: 4x K=128, 32 blocks
    SegP xp = {};
    for (int s = 0; s < 4; s++) {
        xp.A[s] = hch_slot + s * 128;
        xp.W[s] = Wif + (size_t)(s * 128) * IFTOT;
        xp.K[s] = 128; xp.lda[s] = 512;
        xp.Nout[s] = IFTOT;
        xp.coff[s] = XIP + (long)s * XISTRIDE;
    }
    gemm64<<<dim3(8, 1, 4), 256>>>(xp, 4, part);

    k_dnc<<<BB, 256>>>(bif, rvh_slot);
}

extern "C" void kernel_launch(void* const* d_in, const int* in_sizes, int n_in,
                              void* d_out, int out_size) {
    const float* img_feat = (const float*)d_in[0];
    const int*   qst      = (const int*)d_in[1];
    const float* emb      = (const float*)d_in[2];
    const float* img_W    = (const float*)d_in[3];
    const float* img_b    = (const float*)d_in[4];
    const float* q_Wih    = (const float*)d_in[5];
    const float* q_Whh    = (const float*)d_in[6];
    const float* q_b      = (const float*)d_in[7];
    const float* q_Wif    = (const float*)d_in[8];
    const float* q_bif    = (const float*)d_in[9];
    const float* q_Wout   = (const float*)d_in[10];
    const float* q_bout   = (const float*)d_in[11];
    const float* c_Wih    = (const float*)d_in[12];
    const float* c_Whh    = (const float*)d_in[13];
    const float* c_b      = (const float*)d_in[14];
    const float* c_Wif    = (const float*)d_in[15];
    const float* c_bif    = (const float*)d_in[16];
    const float* c_Wout   = (const float*)d_in[17];
    const float* c_bout   = (const float*)d_in[18];
    const float* fc1_W    = (const float*)d_in[19];
    const float* fc1_b    = (const float*)d_in[20];
    const float* fc2_W    = (const float*)d_in[21];
    const float* fc2_b    = (const float*)d_in[22];
    float* out = (float*)d_out;

    float *S, *qv, *pre, *part, *hch, *rvh, *outT, *comb, *last, *fc1;
    cudaGetSymbolAddress((void**)&S, g_state);
    cudaGetSymbolAddress((void**)&qv, g_qv);
    cudaGetSymbolAddress((void**)&pre, g_pre);
    cudaGetSymbolAddress((void**)&part, g_part);
    cudaGetSymbolAddress((void**)&hch, g_hch);
    cudaGetSymbolAddress((void**)&rvh, g_rvh);
    cudaGetSymbolAddress((void**)&outT, g_outT);
    cudaGetSymbolAddress((void**)&comb, g_comb);
    cudaGetSymbolAddress((void**)&last, g_last);
    cudaGetSymbolAddress((void**)&fc1, g_fc1);

    // zero state
    k_zero<<<(STATE_TOT + 255) / 256, 256>>>(S, STATE_TOT);

    // question embedding + hoisted x@Wih_x for all timesteps [1280 x 2048]
    k_embed<<<(BB * TT * EE + 255) / 256, 256>>>(qst, emb);
    {
        SegP pp = {};
        pp.A[0] = qv; pp.W[0] = q_Wih; pp.K[0] = EE; pp.lda[0] = EE;
        pp.Nout[0] = 2048; pp.coff[0] = 0;
        gemm64<<<dim3(32, (BB * TT) / 64, 1), 256>>>(pp, 1, pre);
    }

    // question DNC over T timesteps (out-projection deferred entirely)
    for (int t = 0; t < TT; t++)
        dnc_step(S, part,
                 hch + (size_t)t * BB * HH, rvh + (size_t)t * BB * RWRW,
                 1, t, 0, 0, q_Wih, q_Whh, q_b, q_Wif, q_bif);

    // batched out-GEMM over all timesteps: [hc_hist | rvec_hist] @ Wout, M=1280
    {
        SegP op = {};
        op.A[0] = hch; op.W[0] = q_Wout;                     op.K[0] = 512; op.lda[0] = 512;
        op.A[1] = rvh; op.W[1] = q_Wout + (size_t)512 * CEE; op.K[1] = 256; op.lda[1] = 256;
        op.Nout[0] = CEE; op.coff[0] = 0;
        gemm64<<<dim3(16, TT, 1), 256>>>(op, 2, outT);
        k_qsum<<<(BB * CEE + 255) / 256, 256>>>(q_bout);
    }

    // image encoder (split-K 8) + combine
    {
        SegP ip = {};
        for (int z = 0; z < 8; z++) {
            ip.A[z] = img_feat + (size_t)z * 512;
            ip.W[z] = img_W + (size_t)z * 512 * CEE;
            ip.K[z] = 512;
            ip.lda[z] = 4096;
            ip.Nout[z] = 1024;
            ip.coff[z] = (long)z * 65536;
        }
        gemm64<<<dim3(16, 1, 8), 256>>>(ip, 8, part);
        k_comb<<<BB, 256>>>(img_b, 8);
    }

    // controller DNC (fresh state) — reuse hist slot 0
    k_zero<<<(STATE_TOT + 255) / 256, 256>>>(S, STATE_TOT);
    dnc_step(S, part, hch, rvh, 0, 0, 1, comb,
             c_Wih, c_Whh, c_b, c_Wif, c_bif);
    {
        SegP op = {};
        op.A[0] = hch; op.W[0] = c_Wout;                     op.K[0] = 512; op.lda[0] = 512;
        op.A[1] = rvh; op.W[1] = c_Wout + (size_t)512 * CEE; op.K[1] = 256; op.lda[1] = 256;
        op.Nout[0] = CEE; op.coff[0] = 0;
        gemm64<<<dim3(16, 1, 1), 256>>>(op, 2, outT);
        k_ctrlout<<<(BB * CEE + 255) / 256, 256>>>(c_bout);
    }

    // tail: last -> fc1(tanh) -> fc2
    k_last<<<(BB * (CEE + RWRW) + 255) / 256, 256>>>();
    {
        SegP f1 = {};
        for (int z = 0; z < 8; z++) {
            f1.A[z] = last + (size_t)z * 160;
            f1.W[z] = fc1_W + (size_t)z * 160 * ANSN;
            f1.K[z] = 160;
            f1.lda[z] = CEE + RWRW;
            f1.Nout[z] = ANSN;
            f1.coff[z] = (long)z * 64 * ANSN;
        }
        gemm64<<<dim3(47, 1, 8), 256>>>(f1, 8, part);
        k_red<<<(64 * ANSN + 255) / 256, 256>>>(8, ANSN, fc1_b, fc1, 2);
    }
    {
        SegP f2 = {};
        for (int z = 0; z < 8; z++) {
            f2.A[z] = fc1 + (size_t)z * 375;
            f2.W[z] = fc2_W + (size_t)z * 375 * ANSN;
            f2.K[z] = 375;
            f2.lda[z] = ANSN;
            f2.Nout[z] = ANSN;
            f2.coff[z] = (long)z * 64 * ANSN;
        }
        gemm64<<<dim3(47, 1, 8), 256>>>(f2, 8, part);
        k_red<<<(64 * ANSN + 255) / 256, 256>>>(8, ANSN, fc2_b, out, 0);
    }
}

// round 15
// speedup vs baseline: 2.8201x; 1.0879x over previous
#include <cuda_runtime.h>
#include <math.h>
#include <stdint.h>

// ---------------- constants ----------------
#define BB 64
#define TT 20
#define EE 300
#define CEE 1024
#define ANSN 3000
#define HH 512
#define NN 256
#define WW 64
#define RR 4
#define RWRW 256
#define IFTOT 471
#define CLIPV 20.0f
#define EPSV 1e-6f

// state offsets inside g_state
#define OFF_MEM    0            // B*N*W
#define OFF_LINK   1048576      // B*N*N
#define OFF_PREC   5242880      // B*N
#define OFF_WR     5259264      // B*R*N
#define OFF_WW     5324800      // B*N
#define OFF_USAGE  5341184      // B*N
#define OFF_RVEC   5357568      // B*R*W
#define OFF_H      5373952      // B*H
#define OFF_C      5406720      // B*H
#define STATE_TOT  5439488

// g_part layout (floats)
#define GSTRIDE    131072       // 64*2048 gates partial stride (max 7 -> [0, 917504))
#define XIP        917504       // xi partials base (4 slices)
#define XISTRIDE   30144        // 64*471

// ---------------- device globals ----------------
__device__ __align__(16) float g_state[STATE_TOT];
__device__ __align__(16) float g_qv[BB * TT * EE];
__device__ __align__(16) float g_pre[BB * TT * 2048];
__device__ __align__(16) float g_part[8 * 64 * 3072];
__device__ __align__(16) float g_hch[TT * BB * HH];     // hc history
__device__ __align__(16) float g_rvh[TT * BB * RWRW];   // rvec history
__device__ __align__(16) float g_outT[TT * BB * CEE];   // batched out-GEMM result
__device__ __align__(16) float g_outbuf[BB * CEE];
__device__ __align__(16) float g_qsum[BB * CEE];
__device__ __align__(16) float g_imgf[BB * CEE];
__device__ __align__(16) float g_comb[BB * CEE];
__device__ __align__(16) float g_last[BB * (CEE + RWRW)];
__device__ __align__(16) float g_fc1[BB * ANSN];

// ---------------- helpers ----------------
__device__ __forceinline__ float sigf(float x) { return 1.0f / (1.0f + expf(-x)); }
__device__ __forceinline__ float softplusf(float x) {
    return fmaxf(x, 0.0f) + log1pf(expf(-fabsf(x)));
}
__device__ __forceinline__ float blk_max(float v, volatile float* red, int tid) {
    red[tid] = v; __syncthreads();
    for (int s = 128; s > 0; s >>= 1) {
        if (tid < s) red[tid] = fmaxf((float)red[tid], (float)red[tid + s]);
        __syncthreads();
    }
    float r = red[0]; __syncthreads();
    return r;
}
__device__ __forceinline__ float blk_sum(float v, volatile float* red, int tid) {
    red[tid] = v; __syncthreads();
    for (int s = 128; s > 0; s >>= 1) {
        if (tid < s) red[tid] = (float)red[tid] + (float)red[tid + s];
        __syncthreads();
    }
    float r = red[0]; __syncthreads();
    return r;
}

// ---------------- misc kernels ----------------
__global__ void k_zero(float* p, int n) {
    int i = blockIdx.x * blockDim.x + threadIdx.x;
    if (i < n) p[i] = 0.0f;
}

__global__ void k_embed(const int* __restrict__ qst, const float* __restrict__ emb) {
    int i = blockIdx.x * blockDim.x + threadIdx.x;
    if (i >= BB * TT * EE) return;
    int e = i % EE;
    int bt = i / EE;
    int tok = qst[bt];
    g_qv[i] = tanhf(emb[(size_t)tok * EE + e]);
}

// ---------------- GEMM: 64x64 tile, 256 threads, 4x4 blocking, double-buffered ----------------
struct SegP {
    const float* A[8];
    const float* W[8];
    int K[8];
    int lda[8];
    int Nout[8];
    long coff[8];          // partial output offset into Cout (split mode)
};

__device__ __forceinline__ void ldA4(const float* __restrict__ A, int lda, int row0,
                                     int lm, int lkb, int k0, int K, float* ra) {
    const float* Ap = A + (size_t)(row0 + lm) * lda + k0 + lkb;
#pragma unroll
    for (int u = 0; u < 4; u++)
        ra[u] = (k0 + lkb + u < K) ? Ap[u] : 0.0f;
}

__device__ __forceinline__ void ldW4(const float* __restrict__ W, int Nout, bool nvec,
                                     int col0, int lkk, int lnb, int k0, int K, float* rw) {
    int kg = k0 + lkk;
    int c = col0 + lnb;
    if (nvec && kg < K && c + 3 < Nout) {
        float4 v = *(const float4*)&W[(size_t)kg * Nout + c];
        rw[0] = v.x; rw[1] = v.y; rw[2] = v.z; rw[3] = v.w;
    } else {
#pragma unroll
        for (int u = 0; u < 4; u++)
            rw[u] = (kg < K && c + u < Nout) ? W[(size_t)kg * Nout + c + u] : 0.0f;
    }
}

// gridDim.z>1: one segment per z, output to Cout + coff[z], width Nout[z]
// gridDim.z==1: loop all nseg segments, direct store to Cout (Nout[0]); rows via blockIdx.y
__global__ void gemm64(SegP p, int nseg, float* __restrict__ Cout) {
    __shared__ __align__(16) float As[2][16][68];
    __shared__ __align__(16) float Ws[2][16][68];
    int tid = threadIdx.x;
    int tx = tid & 15;
    int ty = tid >> 4;
    int col0 = blockIdx.x * 64;
    int row0 = blockIdx.y * 64;
    float acc[4][4] = {};

    int z0, z1;
    if (gridDim.z > 1) { z0 = blockIdx.z; z1 = z0 + 1; } else { z0 = 0; z1 = nseg; }
    int Nout = p.Nout[z0];
    if (col0 >= Nout) return;
    bool nvec = ((Nout & 3) == 0);

    int lm = tid >> 2;            // A loader row 0..63
    int lkb = (tid & 3) * 4;      // A loader k offset
    int lkk = tid >> 4;           // W loader k 0..15
    int lnb = (tid & 15) * 4;     // W loader col offset

    for (int z = z0; z < z1; z++) {
        const float* A = p.A[z];
        const float* W = p.W[z];
        int K = p.K[z];
        int lda = p.lda[z];
        float ra[4], rw[4];

        // prologue: chunk 0
        ldA4(A, lda, row0, lm, lkb, 0, K, ra);
        ldW4(W, Nout, nvec, col0, lkk, lnb, 0, K, rw);
#pragma unroll
        for (int u = 0; u < 4; u++) { As[0][lkb + u][lm] = ra[u]; Ws[0][lkk][lnb + u] = rw[u]; }
        __syncthreads();

        int cur = 0;
        for (int k0 = 16; k0 < K; k0 += 16) {
            ldA4(A, lda, row0, lm, lkb, k0, K, ra);
            ldW4(W, Nout, nvec, col0, lkk, lnb, k0, K, rw);
#pragma unroll
            for (int kk = 0; kk < 16; kk++) {
                float4 a = *(const float4*)&As[cur][kk][ty * 4];
                float4 w = *(const float4*)&Ws[cur][kk][tx * 4];
                acc[0][0] += a.x * w.x; acc[0][1] += a.x * w.y;
                acc[0][2] += a.x * w.z; acc[0][3] += a.x * w.w;
                acc[1][0] += a.y * w.x; acc[1][1] += a.y * w.y;
                acc[1][2] += a.y * w.z; acc[1][3] += a.y * w.w;
                acc[2][0] += a.z * w.x; acc[2][1] += a.z * w.y;
                acc[2][2] += a.z * w.z; acc[2][3] += a.z * w.w;
                acc[3][0] += a.w * w.x; acc[3][1] += a.w * w.y;
                acc[3][2] += a.w * w.z; acc[3][3] += a.w * w.w;
            }
            int nxt = cur ^ 1;
#pragma unroll
            for (int u = 0; u < 4; u++) { As[nxt][lkb + u][lm] = ra[u]; Ws[nxt][lkk][lnb + u] = rw[u]; }
            __syncthreads();
            cur = nxt;
        }
        // final chunk compute
#pragma unroll
        for (int kk = 0; kk < 16; kk++) {
            float4 a = *(const float4*)&As[cur][kk][ty * 4];
            float4 w = *(const float4*)&Ws[cur][kk][tx * 4];
            acc[0][0] += a.x * w.x; acc[0][1] += a.x * w.y;
            acc[0][2] += a.x * w.z; acc[0][3] += a.x * w.w;
            acc[1][0] += a.y * w.x; acc[1][1] += a.y * w.y;
            acc[1][2] += a.y * w.z; acc[1][3] += a.y * w.w;
            acc[2][0] += a.z * w.x; acc[2][1] += a.z * w.y;
            acc[2][2] += a.z * w.z; acc[2][3] += a.z * w.w;
            acc[3][0] += a.w * w.x; acc[3][1] += a.w * w.y;
            acc[3][2] += a.w * w.z; acc[3][3] += a.w * w.w;
        }
        if (z + 1 < z1) __syncthreads();
    }

    float* Cbase = Cout + ((gridDim.z > 1) ? p.coff[blockIdx.z] : 0);
#pragma unroll
    for (int i = 0; i < 4; i++) {
        int row = row0 + ty * 4 + i;
#pragma unroll
        for (int j = 0; j < 4; j++) {
            int c = col0 + tx * 4 + j;
            if (c < Nout)
                Cbase[(size_t)row * Nout + c] = acc[i][j];
        }
    }
}

// ---------------- LSTM (single pass) ----------------
__global__ void k_lstm(int nseg, int use_pre, int t, const float* __restrict__ bias,
                       float* __restrict__ hc_out) {
    int idx = blockIdx.x * blockDim.x + threadIdx.x;
    if (idx >= BB * HH) return;
    int b = idx >> 9;
    int j = idx & 511;
    float g[4];
#pragma unroll
    for (int q = 0; q < 4; q++) {
        int col = q * HH + j;
        float v = bias[col];
        if (use_pre) v += g_pre[((size_t)(b * TT + t)) * 2048 + col];
        for (int z = 0; z < nseg; z++) v += g_part[(size_t)z * GSTRIDE + b * 2048 + col];
        g[q] = v;
    }
    float cc = sigf(g[1]) * g_state[OFF_C + idx] + sigf(g[0]) * tanhf(g[2]);
    float hh = sigf(g[3]) * tanhf(cc);
    g_state[OFF_C + idx] = cc;
    g_state[OFF_H + idx] = hh;
    hc_out[idx] = fminf(fmaxf(hh, -CLIPV), CLIPV);
}

// ---------------- batched out epilogue: qsum[b,c] = sum_t clip(outT + bias) ----------------
__global__ void k_qsum(const float* __restrict__ bias) {
    int idx = blockIdx.x * blockDim.x + threadIdx.x;
    if (idx >= BB * CEE) return;
    int b = idx >> 10;
    int c = idx & 1023;
    float bs = bias[c];
    float s = 0;
    for (int t = 0; t < TT; t++) {
        float v = g_outT[((size_t)t * BB + b) * CEE + c] + bs;
        s += fminf(fmaxf(v, -CLIPV), CLIPV);
    }
    g_qsum[idx] = s;
}

// controller out epilogue: outbuf = clip(outT0 + bias)
__global__ void k_ctrlout(const float* __restrict__ bias) {
    int idx = blockIdx.x * blockDim.x + threadIdx.x;
    if (idx >= BB * CEE) return;
    int c = idx & 1023;
    float v = g_outT[idx] + bias[c];
    g_outbuf[idx] = fminf(fmaxf(v, -CLIPV), CLIPV);
}

// ---------------- reduction / pointwise kernels ----------------
// act: 0 none, 2 tanh
__global__ void k_red(int nseg, int Nout, const float* __restrict__ bias,
                      float* __restrict__ out, int act) {
    int idx = blockIdx.x * blockDim.x + threadIdx.x;
    if (idx >= 64 * Nout) return;
    int j = idx % Nout;
    float v = bias[j];
    for (int z = 0; z < nseg; z++) v += g_part[(size_t)z * 64 * Nout + idx];
    if (act == 2) v = tanhf(v);
    out[idx] = v;
}

__global__ void k_comb(const float* __restrict__ img_b, int nseg) {
    __shared__ float red[256];
    int b = blockIdx.x;
    int tid = threadIdx.x;
    float s = 0;
    for (int j = tid; j < CEE; j += 256) {
        float v = img_b[j];
        for (int z = 0; z < nseg; z++) v += g_part[(size_t)z * 64 * 1024 + b * 1024 + j];
        g_imgf[b * CEE + j] = v;
        s += v * v;
    }
    float tot = blk_sum(s, red, tid);
    float inv = rsqrtf(tot);
    for (int j = tid; j < CEE; j += 256) {
        float v = g_imgf[b * CEE + j] * inv;
        g_comb[b * CEE + j] = tanhf(v * g_qsum[b * CEE + j] * (1.0f / (float)TT));
    }
}

__global__ void k_last() {
    int idx = blockIdx.x * blockDim.x + threadIdx.x;
    if (idx >= BB * (CEE + RWRW)) return;
    int b = idx / (CEE + RWRW);
    int j = idx % (CEE + RWRW);
    float v = (j < CEE) ? g_outbuf[b * CEE + j] : g_state[OFF_RVEC + b * 256 + (j - CEE)];
    g_last[idx] = tanhf(v);
}

// ---------------- fused per-batch DNC memory kernel ----------------
__global__ void k_dnc(const float* __restrict__ bif, float* __restrict__ rvh_slot) {
    __shared__ float wro[4][256];
    __shared__ float sh_rk[256];
    __shared__ float sh_wkey[64], sh_erase[64], sh_wvec[64];
    __shared__ float sh_rstr[4], sh_free[4];
    __shared__ float sh_mraw[12], sh_modes[12];
    __shared__ float sh_scal[4];   // 0 wstr, 1 allocg, 2 writeg, 3 wwsum
    __shared__ float sh_alloc[256], sh_ww[256], sh_prec[256];
    __shared__ float red[256];
    __shared__ float sv[256];
    __shared__ float sc[256];
    __shared__ float stage[4][4][256];   // [row-group][r][col]
    __shared__ float bws[4][256], fws[4][256], crs[4][256], wsn[4][256];

    int b = blockIdx.x;
    int tid = threadIdx.x;

#pragma unroll
    for (int r = 0; r < 4; r++)
        wro[r][tid] = g_state[OFF_WR + b * 1024 + r * 256 + tid];
    sh_prec[tid] = g_state[OFF_PREC + b * 256 + tid];

    // ---- Phase A: xi reduce + interface transforms ----
    for (int t = tid; t < IFTOT; t += 256) {
        float v = bif[t];
        for (int z = 0; z < 4; z++)
            v += g_part[XIP + (size_t)z * XISTRIDE + b * IFTOT + t];
        if (t < 256)       sh_rk[t] = tanhf(v);
        else if (t < 260)  sh_rstr[t - 256] = softplusf(v);
        else if (t < 324)  sh_wkey[t - 260] = tanhf(v);
        else if (t == 324) sh_scal[0] = softplusf(v);
        else if (t < 389)  sh_erase[t - 325] = sigf(v);
        else if (t < 453)  sh_wvec[t - 389] = tanhf(v);
        else if (t < 457)  sh_free[t - 453] = sigf(v);
        else if (t == 457) sh_scal[1] = sigf(v);
        else if (t == 458) sh_scal[2] = sigf(v);
        else               sh_mraw[t - 459] = v;
    }
    __syncthreads();
    if (tid < 4) {
        float v0 = sh_mraw[tid * 3], v1 = sh_mraw[tid * 3 + 1], v2 = sh_mraw[tid * 3 + 2];
        float m = fmaxf(v0, fmaxf(v1, v2));
        float e0 = expf(v0 - m), e1 = expf(v1 - m), e2 = expf(v2 - m);
        float s = e0 + e1 + e2;
        sh_modes[tid * 3] = e0 / s;
        sh_modes[tid * 3 + 1] = e1 / s;
        sh_modes[tid * 3 + 2] = e2 / s;
    }
    __syncthreads();

    // ---- Phase B: usage update + counting-rank stable argsort + alloc ----
    float psi = 1.0f;
#pragma unroll
    for (int r = 0; r < 4; r++)
        psi *= 1.0f - sh_free[r] * wro[r][tid];
    float uo = g_state[OFF_USAGE + b * 256 + tid];
    float wo = g_state[OFF_WW + b * 256 + tid];
    float u = (uo + wo - uo * wo) * psi;
    g_state[OFF_USAGE + b * 256 + tid] = u;
    sv[tid] = u;
    __syncthreads();
    // stable rank: #{j : u_j < u_i  or (u_j == u_i and j < i)}
    int rank = 0;
#pragma unroll 8
    for (int j = 0; j < 256; j++) {
        float uj = sv[j];
        rank += (uj < u) || (uj == u && j < tid);
    }
    sc[rank] = u;                  // scatter sorted values
    __syncthreads();
    // inclusive product scan over sorted values
    for (int off = 1; off < 256; off <<= 1) {
        float tval = (tid >= off) ? sc[tid - off] : 1.0f;
        __syncthreads();
        sc[tid] *= tval;
        __syncthreads();
    }
    float cpe = (rank == 0) ? 1.0f : sc[rank - 1];
    sh_alloc[tid] = (1.0f - u) * cpe;
    __syncthreads();

    // ---- Phase C: write content weights + ww + wwsum (OLD mem) ----
    float kn = 0;
#pragma unroll 8
    for (int w = 0; w < 64; w++) kn += sh_wkey[w] * sh_wkey[w];
    kn = sqrtf(kn) + EPSV;
    float dot = 0, mn0 = 0;
    size_t mbase = (size_t)OFF_MEM + (size_t)b * NN * WW;
#pragma unroll 8
    for (int w = 0; w < 64; w++) {
        float m = g_state[mbase + (size_t)tid * WW + w];
        dot += m * sh_wkey[w];
        mn0 += m * m;
    }
    float sim = sh_scal[0] * dot / ((sqrtf(mn0) + EPSV) * kn);
    float mx = blk_max(sim, red, tid);
    float e = expf(sim - mx);
    float sm = blk_sum(e, red, tid);
    float cwv = e / sm;
    float ag = sh_scal[1], wg = sh_scal[2];
    float wwv = wg * (ag * sh_alloc[tid] + (1.0f - ag) * cwv);
    sh_ww[tid] = wwv;
    g_state[OFF_WW + b * 256 + tid] = wwv;
    float wws = blk_sum(wwv, red, tid);
    if (tid == 0) sh_scal[3] = wws;
    __syncthreads();

    // ---- Phase D: memory update (float4) ----
    for (int i = tid * 4; i < NN * WW; i += 1024) {
        float4 m = *(const float4*)&g_state[mbase + i];
        int n = i >> 6, w = i & 63;
        float wwn = sh_ww[n];
        m.x = m.x * (1.0f - wwn * sh_erase[w])     + wwn * sh_wvec[w];
        m.y = m.y * (1.0f - wwn * sh_erase[w + 1]) + wwn * sh_wvec[w + 1];
        m.z = m.z * (1.0f - wwn * sh_erase[w + 2]) + wwn * sh_wvec[w + 2];
        m.w = m.w * (1.0f - wwn * sh_erase[w + 3]) + wwn * sh_wvec[w + 3];
        *(float4*)&g_state[mbase + i] = m;
    }

    // ---- Phase E: link update (float4) + staged bw + prec ----
    {
        int cg = tid & 63;          // column group (4 cols)
        int pr = tid >> 6;          // row group (64 rows)
        int j0 = cg * 4;
        size_t lb = (size_t)OFF_LINK + (size_t)b * 65536;
        float wwj0 = sh_ww[j0],     wwj1 = sh_ww[j0 + 1];
        float wwj2 = sh_ww[j0 + 2], wwj3 = sh_ww[j0 + 3];
        float pj0 = sh_prec[j0],     pj1 = sh_prec[j0 + 1];
        float pj2 = sh_prec[j0 + 2], pj3 = sh_prec[j0 + 3];
        float bwa[4][4] = {};
        int pend = pr * 64 + 64;
#pragma unroll 2
        for (int p = pr * 64; p < pend; p++) {
            float4 l = *(const float4*)&g_state[lb + (size_t)p * 256 + j0];
            float wi = sh_ww[p];
            float f = 1.0f - wi;
            float4 ln;
            ln.x = (p == j0)     ? 0.0f : (f - wwj0) * l.x + wi * pj0;
            ln.y = (p == j0 + 1) ? 0.0f : (f - wwj1) * l.y + wi * pj1;
            ln.z = (p == j0 + 2) ? 0.0f : (f - wwj2) * l.z + wi * pj2;
            ln.w = (p == j0 + 3) ? 0.0f : (f - wwj3) * l.w + wi * pj3;
            *(float4*)&g_state[lb + (size_t)p * 256 + j0] = ln;
#pragma unroll
            for (int r = 0; r < 4; r++) {
                float w = wro[r][p];
                bwa[r][0] += ln.x * w; bwa[r][1] += ln.y * w;
                bwa[r][2] += ln.z * w; bwa[r][3] += ln.w * w;
            }
        }
#pragma unroll
        for (int r = 0; r < 4; r++) {
            stage[pr][r][j0]     = bwa[r][0];
            stage[pr][r][j0 + 1] = bwa[r][1];
            stage[pr][r][j0 + 2] = bwa[r][2];
            stage[pr][r][j0 + 3] = bwa[r][3];
        }
        g_state[OFF_PREC + b * 256 + tid] = (1.0f - sh_scal[3]) * sh_prec[tid] + sh_ww[tid];
    }
    __syncthreads();
#pragma unroll
    for (int r = 0; r < 4; r++)
        bws[r][tid] = stage[0][r][tid] + stage[1][r][tid] + stage[2][r][tid] + stage[3][r][tid];

    // ---- Phase F: fw (new link, old wr), float4 ----
    {
        int warp = tid >> 5, lane = tid & 31;
        size_t lb = (size_t)OFF_LINK + (size_t)b * 65536;
        int j0 = lane * 8;
        for (int i = warp * 32; i < warp * 32 + 32; i++) {
            float4 la = *(const float4*)&g_state[lb + (size_t)i * 256 + j0];
            float4 lc = *(const float4*)&g_state[lb + (size_t)i * 256 + j0 + 4];
            float acc[4];
#pragma unroll
            for (int r = 0; r < 4; r++) {
                acc[r] = la.x * wro[r][j0]     + la.y * wro[r][j0 + 1]
                       + la.z * wro[r][j0 + 2] + la.w * wro[r][j0 + 3]
                       + lc.x * wro[r][j0 + 4] + lc.y * wro[r][j0 + 5]
                       + lc.z * wro[r][j0 + 6] + lc.w * wro[r][j0 + 7];
            }
#pragma unroll
            for (int r = 0; r < 4; r++) {
#pragma unroll
                for (int off = 16; off > 0; off >>= 1)
                    acc[r] += __shfl_xor_sync(0xffffffff, acc[r], off);
            }
            if (lane == 0) {
#pragma unroll
                for (int r = 0; r < 4; r++) fws[r][i] = acc[r];
            }
        }
    }
    __syncthreads();

    // ---- Phase G: read content weights (NEW mem) ----
    float kn2[4];
#pragma unroll
    for (int r = 0; r < 4; r++) {
        float s = 0;
#pragma unroll 8
        for (int w = 0; w < 64; w++) s += sh_rk[r * 64 + w] * sh_rk[r * 64 + w];
        kn2[r] = sqrtf(s) + EPSV;
    }
    float mn = 0;
    float dots[4] = {0, 0, 0, 0};
#pragma unroll 4
    for (int w = 0; w < 64; w++) {
        float m = g_state[mbase + (size_t)tid * WW + w];
        mn += m * m;
#pragma unroll
        for (int r = 0; r < 4; r++) dots[r] += m * sh_rk[r * 64 + w];
    }
    float mnorm = sqrtf(mn) + EPSV;
    for (int r = 0; r < 4; r++) {
        float simr = sh_rstr[r] * dots[r] / (mnorm * kn2[r]);
        float mxr = blk_max(simr, red, tid);
        float er = expf(simr - mxr);
        float smr = blk_sum(er, red, tid);
        crs[r][tid] = er / smr;
    }

    // ---- Phase H: wr update + rvec ----
#pragma unroll
    for (int r = 0; r < 4; r++) {
        float v = sh_modes[r * 3 + 0] * bws[r][tid]
                + sh_modes[r * 3 + 1] * crs[r][tid]
                + sh_modes[r * 3 + 2] * fws[r][tid];
        wsn[r][tid] = v;
        g_state[OFF_WR + b * 1024 + r * 256 + tid] = v;
    }
    __syncthreads();
    {
        int r2 = tid >> 6;
        int w = tid & 63;
        float acc = 0;
#pragma unroll 4
        for (int n = 0; n < 256; n++)
            acc += wsn[r2][n] * g_state[mbase + (size_t)n * 64 + w];
        g_state[OFF_RVEC + b * 256 + tid] = acc;
        rvh_slot[b * 256 + tid] = acc;
    }
}

// ---------------- host ----------------
// One DNC recurrence step: 4 launches (gates, lstm, xi, dnc).
static void dnc_step(float* S, float* part, float* hch_slot, float* rvh_slot,
                     int use_pre, int t, int is_controller, const float* comb,
                     const float* Wih, const float* Whh, const float* bgate,
                     const float* Wif, const float* bif) {
    SegP gp = {};
    int ng;
    if (!is_controller) {
        // gates: rvec 2x128 + h 4x128 = 6 segments
        for (int u = 0; u < 2; u++) {
            gp.A[u] = S + OFF_RVEC + u * 128;
            gp.W[u] = Wih + (size_t)(EE + u * 128) * 2048;
            gp.K[u] = 128; gp.lda[u] = 256;
        }
        for (int u = 0; u < 4; u++) {
            gp.A[2 + u] = S + OFF_H + u * 128;
            gp.W[2 + u] = Whh + (size_t)(u * 128) * 2048;
            gp.K[2 + u] = 128; gp.lda[2 + u] = 512;
        }
        ng = 6;
    } else {
        // gates: comb 4x256 + rvec 1x256 + h 2x256 = 7 segments
        for (int u = 0; u < 4; u++) {
            gp.A[u] = comb + u * 256;
            gp.W[u] = Wih + (size_t)(u * 256) * 2048;
            gp.K[u] = 256; gp.lda[u] = 1024;
        }
        gp.A[4] = S + OFF_RVEC; gp.W[4] = Wih + (size_t)1024 * 2048; gp.K[4] = 256; gp.lda[4] = 256;
        for (int u = 0; u < 2; u++) {
            gp.A[5 + u] = S + OFF_H + u * 256;
            gp.W[5 + u] = Whh + (size_t)(u * 256) * 2048;
            gp.K[5 + u] = 256; gp.lda[5 + u] = 512;
        }
        ng = 7;
    }
    for (int u = 0; u < 8; u++) { gp.Nout[u] = 2048; gp.coff[u] = (long)u * GSTRIDE; }
    gemm64<<<dim3(32, 1, ng), 256>>>(gp, ng, part);

    k_lstm<<<(BB * HH + 255) / 256, 256>>>(ng, use_pre, t, bgate, hch_slot);

    // xi GEMM: 4x K=128, 32 blocks
    SegP xp = {};
    for (int s = 0; s < 4; s++) {
        xp.A[s] = hch_slot + s * 128;
        xp.W[s] = Wif + (size_t)(s * 128) * IFTOT;
        xp.K[s] = 128; xp.lda[s] = 512;
        xp.Nout[s] = IFTOT;
        xp.coff[s] = XIP + (long)s * XISTRIDE;
    }
    gemm64<<<dim3(8, 1, 4), 256>>>(xp, 4, part);

    k_dnc<<<BB, 256>>>(bif, rvh_slot);
}

extern "C" void kernel_launch(void* const* d_in, const int* in_sizes, int n_in,
                              void* d_out, int out_size) {
    const float* img_feat = (const float*)d_in[0];
    const int*   qst      = (const int*)d_in[1];
    const float* emb      = (const float*)d_in[2];
    const float* img_W    = (const float*)d_in[3];
    const float* img_b    = (const float*)d_in[4];
    const float* q_Wih    = (const float*)d_in[5];
    const float* q_Whh    = (const float*)d_in[6];
    const float* q_b      = (const float*)d_in[7];
    const float* q_Wif    = (const float*)d_in[8];
    const float* q_bif    = (const float*)d_in[9];
    const float* q_Wout   = (const float*)d_in[10];
    const float* q_bout   = (const float*)d_in[11];
    const float* c_Wih    = (const float*)d_in[12];
    const float* c_Whh    = (const float*)d_in[13];
    const float* c_b      = (const float*)d_in[14];
    const float* c_Wif    = (const float*)d_in[15];
    const float* c_bif    = (const float*)d_in[16];
    const float* c_Wout   = (const float*)d_in[17];
    const float* c_bout   = (const float*)d_in[18];
    const float* fc1_W    = (const float*)d_in[19];
    const float* fc1_b    = (const float*)d_in[20];
    const float* fc2_W    = (const float*)d_in[21];
    const float* fc2_b    = (const float*)d_in[22];
    float* out = (float*)d_out;

    float *S, *qv, *pre, *part, *hch, *rvh, *outT, *comb, *last, *fc1;
    cudaGetSymbolAddress((void**)&S, g_state);
    cudaGetSymbolAddress((void**)&qv, g_qv);
    cudaGetSymbolAddress((void**)&pre, g_pre);
    cudaGetSymbolAddress((void**)&part, g_part);
    cudaGetSymbolAddress((void**)&hch, g_hch);
    cudaGetSymbolAddress((void**)&rvh, g_rvh);
    cudaGetSymbolAddress((void**)&outT, g_outT);
    cudaGetSymbolAddress((void**)&comb, g_comb);
    cudaGetSymbolAddress((void**)&last, g_last);
    cudaGetSymbolAddress((void**)&fc1, g_fc1);

    // zero state
    k_zero<<<(STATE_TOT + 255) / 256, 256>>>(S, STATE_TOT);

    // question embedding + hoisted x@Wih_x for all timesteps [1280 x 2048]
    k_embed<<<(BB * TT * EE + 255) / 256, 256>>>(qst, emb);
    {
        SegP pp = {};
        pp.A[0] = qv; pp.W[0] = q_Wih; pp.K[0] = EE; pp.lda[0] = EE;
        pp.Nout[0] = 2048; pp.coff[0] = 0;
        gemm64<<<dim3(32, (BB * TT) / 64, 1), 256>>>(pp, 1, pre);
    }

    // question DNC over T timesteps (out-projection deferred entirely)
    for (int t = 0; t < TT; t++)
        dnc_step(S, part,
                 hch + (size_t)t * BB * HH, rvh + (size_t)t * BB * RWRW,
                 1, t, 0, 0, q_Wih, q_Whh, q_b, q_Wif, q_bif);

    // batched out-GEMM over all timesteps: [hc_hist | rvec_hist] @ Wout, M=1280
    {
        SegP op = {};
        op.A[0] = hch; op.W[0] = q_Wout;                     op.K[0] = 512; op.lda[0] = 512;
        op.A[1] = rvh; op.W[1] = q_Wout + (size_t)512 * CEE; op.K[1] = 256; op.lda[1] = 256;
        op.Nout[0] = CEE; op.coff[0] = 0;
        gemm64<<<dim3(16, TT, 1), 256>>>(op, 2, outT);
        k_qsum<<<(BB * CEE + 255) / 256, 256>>>(q_bout);
    }

    // image encoder (split-K 8) + combine
    {
        SegP ip = {};
        for (int z = 0; z < 8; z++) {
            ip.A[z] = img_feat + (size_t)z * 512;
            ip.W[z] = img_W + (size_t)z * 512 * CEE;
            ip.K[z] = 512;
            ip.lda[z] = 4096;
            ip.Nout[z] = 1024;
            ip.coff[z] = (long)z * 65536;
        }
        gemm64<<<dim3(16, 1, 8), 256>>>(ip, 8, part);
        k_comb<<<BB, 256>>>(img_b, 8);
    }

    // controller DNC (fresh state) — reuse hist slot 0
    k_zero<<<(STATE_TOT + 255) / 256, 256>>>(S, STATE_TOT);
    dnc_step(S, part, hch, rvh, 0, 0, 1, comb,
             c_Wih, c_Whh, c_b, c_Wif, c_bif);
    {
        SegP op = {};
        op.A[0] = hch; op.W[0] = c_Wout;                     op.K[0] = 512; op.lda[0] = 512;
        op.A[1] = rvh; op.W[1] = c_Wout + (size_t)512 * CEE; op.K[1] = 256; op.lda[1] = 256;
        op.Nout[0] = CEE; op.coff[0] = 0;
        gemm64<<<dim3(16, 1, 1), 256>>>(op, 2, outT);
        k_ctrlout<<<(BB * CEE + 255) / 256, 256>>>(c_bout);
    }

    // tail: last -> fc1(tanh) -> fc2
    k_last<<<(BB * (CEE + RWRW) + 255) / 256, 256>>>();
    {
        SegP f1 = {};
        for (int z = 0; z < 8; z++) {
            f1.A[z] = last + (size_t)z * 160;
            f1.W[z] = fc1_W + (size_t)z * 160 * ANSN;
            f1.K[z] = 160;
            f1.lda[z] = CEE + RWRW;
            f1.Nout[z] = ANSN;
            f1.coff[z] = (long)z * 64 * ANSN;
        }
        gemm64<<<dim3(47, 1, 8), 256>>>(f1, 8, part);
        k_red<<<(64 * ANSN + 255) / 256, 256>>>(8, ANSN, fc1_b, fc1, 2);
    }
    {
        SegP f2 = {};
        for (int z = 0; z < 8; z++) {
            f2.A[z] = fc1 + (size_t)z * 375;
            f2.W[z] = fc2_W + (size_t)z * 375 * ANSN;
            f2.K[z] = 375;
            f2.lda[z] = ANSN;
            f2.Nout[z] = ANSN;
            f2.coff[z] = (long)z * 64 * ANSN;
        }
        gemm64<<<dim3(47, 1, 8), 256>>>(f2, 8, part);
        k_red<<<(64 * ANSN + 255) / 256, 256>>>(8, ANSN, fc2_b, out, 0);
    }
}